// round 11
// baseline (speedup 1.0000x reference)
#include <cuda_runtime.h>
#include <cuda_bf16.h>
#include <math.h>

// ============================================================================
// S2ConvNet forward on GB300.
//   x(16,1,128,128) f32 -> out(16,10) f32
//   B_IN=64, B_L1=16, B_L2=8, F1=64, F2=128, BATCH=16
// Pipeline:
//   tables -> s2 DFT -> Fx -> FyC -> fused (iSO3 -> relu -> fSO3 spectrum)
//   -> Fx2 -> Fy2 -> Fz2 GEMM -> fused (iSO3 -> relu -> mean) -> linear head
// All scratch is __device__ globals; every kernel is deterministic and
// graph-capturable (plain launches on the default stream).
// ============================================================================

#define PI_D 3.14159265358979323846

#define NP1   256      // sum_{l<16}(2l+1)
#define NP2F  5456     // sum_{l<16}(2l+1)^2
#define NP2   680      // sum_{l<8}(2l+1)^2
#define BF    1024     // BATCH*F1
#define BO    2048     // BATCH*F2

__constant__ int c_off2[17] = {0,1,10,35,84,165,286,455,680,969,1330,1771,
                               2300,2925,3654,4495,5456};

// ------------------------- device global scratch ---------------------------
__device__ float  g_Win[128];
__device__ float  g_Wl1[32];
__device__ float  g_Wl2[16];
__device__ float  g_dcol[256*128];          // [p1][k]  d^l_{m0}(beta_in_k)
__device__ float  g_dL1[32*NP2F];           // [k][p2f] full d, L1 betas
__device__ float  g_dL2[16*NP2];            // [k][p2]  full d, L2 betas
__device__ float  g_dG[3*NP2F];             // [gbeta][p2f] full d, grid betas
__device__ float  g_cf1[32*NP2];            // 2pi*Wl1[k]*dL1 (l<8)
__device__ int    g_mnidx[NP2];             // p2 -> (m+7)*15+(n+7)
__device__ float2 g_psi3[NP2*192];          // conj(psi_SO3)
__device__ float2 g_xf1[31*2048];           // [m+15][b*128+k]
__device__ float2 g_Fx[16*256];             // [b][p1]
__device__ float2 g_FyC[64*256];            // [o][p1]  (conj applied)
__device__ float2 g_xf2[32u*1024u*225u];    // [k][bf][mn]  (59 MB)
__device__ float2 g_Fx2[NP2*BF];            // [p2][bf]
__device__ float2 g_Fy2[NP2*8192];          // [p2][i*128+o] (conj applied)
__device__ float2 g_Fz2[BO*NP2];            // [b*128+o][p2]
__device__ float  g_feat[BO];

// ------------------------- Wigner small-d (fp64) ---------------------------
// d^l_{m,n}(beta), basis exp(-i beta Jy), ascending m. Standard convention.
__device__ double wigd(int l, int m, int n, double beta) {
    double fact[32];
    fact[0] = 1.0;
    for (int i = 1; i < 32; i++) fact[i] = fact[i-1] * (double)i;
    double ch = cos(0.5*beta), sh = sin(0.5*beta);
    int smin = n - m; if (smin < 0) smin = 0;
    int smax = l + n; if (l - m < smax) smax = l - m;
    double pref = sqrt(fact[l+m]*fact[l-m]*fact[l+n]*fact[l-n]);
    double sum = 0.0;
    for (int s = smin; s <= smax; s++) {
        int ae = 2*l + n - m - 2*s;
        int be = m - n + 2*s;
        double pc = 1.0; for (int i = 0; i < ae; i++) pc *= ch;
        double ps = 1.0; for (int i = 0; i < be; i++) ps *= sh;
        double t = pref/(fact[l+n-s]*fact[s]*fact[m-n+s]*fact[l-m-s])*pc*ps;
        sum += ((m-n+s)&1) ? -t : t;
    }
    return sum;
}

__device__ __forceinline__ void dec_p2(int p, int* lo, int* mo, int* no) {
    int l = 0;
    while (c_off2[l+1] <= p) l++;
    int r = p - c_off2[l], D = 2*l+1;
    *lo = l; *mo = r/D - l; *no = r%D - l;
}

// ------------------------- table generation --------------------------------
__global__ void k_tables() {
    int id = blockIdx.x*blockDim.x + threadIdx.x;
    if (id < 32768) {                                   // g_dcol
        int p1 = id >> 7, k = id & 127;
        int l = 0; while ((l+1)*(l+1) <= p1) l++;
        int m = p1 - l*l - l;
        g_dcol[id] = (float)wigd(l, m, 0, PI_D*(2*k+1)/256.0);
        return;
    }
    id -= 32768;
    if (id < 32*NP2F) {                                 // g_dL1
        int k = id / NP2F, p = id % NP2F;
        int l, m, n; dec_p2(p, &l, &m, &n);
        g_dL1[id] = (float)wigd(l, m, n, PI_D*(2*k+1)/64.0);
        return;
    }
    id -= 32*NP2F;
    if (id < 16*NP2) {                                  // g_dL2
        int k = id / NP2, p = id % NP2;
        int l, m, n; dec_p2(p, &l, &m, &n);
        g_dL2[id] = (float)wigd(l, m, n, PI_D*(2*k+1)/32.0);
        return;
    }
    id -= 16*NP2;
    if (id < 3*NP2F) {                                  // g_dG
        int gi = id / NP2F, p = id % NP2F;
        int l, m, n; dec_p2(p, &l, &m, &n);
        g_dG[id] = (float)wigd(l, m, n, (gi+1)*PI_D/24.0);
    }
}

__global__ void k_weights() {
    int id = threadIdx.x;
    int b, j; float* dst;
    if (id < 128)      { b = 64; j = id;       dst = &g_Win[j]; }
    else if (id < 160) { b = 16; j = id - 128; dst = &g_Wl1[j]; }
    else if (id < 176) { b = 8;  j = id - 160; dst = &g_Wl2[j]; }
    else return;
    double s = 0.0;
    for (int l2 = 0; l2 < b; l2++)
        s += sin((2.0*j+1)*(2.0*l2+1)*PI_D/(4.0*b)) / (2.0*l2+1);
    *dst = (float)((2.0/b)*sin(PI_D*(2*j+1)/(4.0*b))*s);
}

__global__ void k_prep() {
    int id = blockIdx.x*256 + threadIdx.x;              // 32*680 = 21760
    if (id < 32*NP2) {
        int k = id / NP2, p = id % NP2;
        g_cf1[id] = (float)(2.0*PI_D) * g_Wl1[k] * g_dL1[k*NP2F + p];
    }
    if (id < NP2) {
        int l, m, n; dec_p2(id, &l, &m, &n);
        g_mnidx[id] = (m+7)*15 + (n+7);
    }
}

__global__ void k_psi3gen() {
    int id = blockIdx.x*256 + threadIdx.x;              // 680*192
    if (id >= NP2*192) return;
    int p2 = id / 192, g = id % 192;
    int l, m, n; dec_p2(p2, &l, &m, &n);
    int ia = (g>>3)&7, ic = g&7, ib = g>>6;
    float d = g_dG[ib*NP2F + p2];
    int ph = ((m-n)*ia + n*ic + 160) & 7;               // conj: e^{+i(m a + n g)}
    float s, c; sincosf((float)ph * (float)(PI_D/4.0), &s, &c);
    g_psi3[id] = make_float2(d*c, d*s);
}

// ------------------------- S2 stage ----------------------------------------
__global__ void k_dft1(const float* __restrict__ x) {
    int bid = blockIdx.x;                               // b*128 + k
    __shared__ float xs[128], tcr[128], tci[128];
    int tid = threadIdx.x;                              // 64
    xs[tid]      = x[bid*128 + tid];
    xs[tid+64]   = x[bid*128 + tid + 64];
    float s, c;
    sincosf((float)tid      * (float)(-2.0*PI_D/128.0), &s, &c); tcr[tid]=c;    tci[tid]=s;
    sincosf((float)(tid+64) * (float)(-2.0*PI_D/128.0), &s, &c); tcr[tid+64]=c; tci[tid+64]=s;
    __syncthreads();
    if (tid < 31) {
        int m = tid - 15;
        float ar = 0.f, ai = 0.f;
        for (int a = 0; a < 128; a++) {
            int j = ((m+128)*a) & 127;
            ar += xs[a]*tcr[j];
            ai += xs[a]*tci[j];
        }
        g_xf1[tid*2048 + bid] = make_float2(ar, ai);
    }
}

__global__ void k_fx() {
    int id = blockIdx.x*256 + threadIdx.x;              // 4096
    if (id >= 4096) return;
    int b = id & 15, p1 = id >> 4;
    int l = 0; while ((l+1)*(l+1) <= p1) l++;
    int m = p1 - l*l - l;
    float sr = 0.f, si = 0.f;
    for (int kk = 0; kk < 128; kk++) {
        float w = g_Win[kk]*g_dcol[p1*128 + kk];
        float2 v = g_xf1[(m+15)*2048 + b*128 + kk];
        sr += w*v.x; si += w*v.y;
    }
    float sc = (float)(2.0*PI_D/128.0);
    g_Fx[b*256 + p1] = make_float2(sr*sc, si*sc);
}

__global__ void k_fyc(const float* __restrict__ w1) {
    int id = blockIdx.x*256 + threadIdx.x;              // 16384
    if (id >= 16384) return;
    int p1 = id >> 6, o = id & 63;
    int l = 0; while ((l+1)*(l+1) <= p1) l++;
    int m = p1 - l*l - l;
    int dbase = c_off2[l] + (m+l)*(2*l+1) + l;          // column n=0
    float sr = 0.f, si = 0.f;
    for (int g = 0; g < 24; g++) {
        int ib = g >> 3, ia = g & 7;
        float d = g_dG[ib*NP2F + dbase];
        int ph = (m*ia + 120) & 7;                      // conj: e^{+i m a}
        float sn, cs; sincosf((float)ph*(float)(PI_D/4.0), &sn, &cs);
        float wv = w1[o*24 + g];
        sr += wv*d*cs;
        si += wv*d*sn;
    }
    g_FyC[o*256 + p1] = make_float2(sr, si);
}

// ------------------------- fused middle stage ------------------------------
// per (b,f,k): S build -> iDFT2(31->32) -> relu -> fDFT2(32->15x15)
__global__ void __launch_bounds__(256) k_mid() {
    int bid = blockIdx.x;                               // 32768
    int k = bid & 31, f = (bid>>5)&63, b = bid>>11;
    __shared__ float  ds[NP2F];
    __shared__ float2 fxs[256], fycs[256];
    __shared__ float2 Ss[31*32];
    __shared__ float2 Ts[31*32];
    __shared__ float  ys[1024];
    __shared__ float2 Us[8*32];
    __shared__ float  twr[32], twi[32];
    int tid = threadIdx.x;

    for (int i = tid; i < NP2F; i += 256) ds[i] = g_dL1[k*NP2F + i];
    fxs[tid]  = g_Fx[b*256 + tid];
    fycs[tid] = g_FyC[f*256 + tid];
    if (tid < 32) {
        float s, c; sincosf((float)tid*(float)(2.0*PI_D/32.0), &s, &c);
        twr[tid] = c; twi[tid] = s;                     // e^{+2pi i j/32}
    }
    __syncthreads();

    // S[m,n] = sum_l (2l+1) d^l_{mn}(bk) Fx[l,m] FyC[l,n]
    for (int idx = tid; idx < 961; idx += 256) {
        int mi = idx/31, ni = idx%31, m = mi-15, n = ni-15;
        int am = m < 0 ? -m : m, an = n < 0 ? -n : n;
        int lmin = am > an ? am : an;
        float sr = 0.f, si = 0.f;
        for (int l = lmin; l < 16; l++) {
            int D = 2*l+1;
            float w = (float)D * ds[c_off2[l] + (m+l)*D + (n+l)];
            float2 a  = fxs[l*l + l + m];
            float2 bb = fycs[l*l + l + n];
            sr += w*(a.x*bb.x - a.y*bb.y);
            si += w*(a.x*bb.y + a.y*bb.x);
        }
        Ss[mi*32 + ni] = make_float2(sr, si);
    }
    __syncthreads();

    // T[m,c] = sum_n S[m,n] e^{+i n c 2pi/32}
    for (int idx = tid; idx < 992; idx += 256) {
        int mi = idx >> 5, c = idx & 31;
        float tr = 0.f, ti = 0.f;
        for (int ni = 0; ni < 31; ni++) {
            int j = ((ni+17)*c) & 31;
            float2 s = Ss[mi*32 + ni];
            tr += s.x*twr[j] - s.y*twi[j];
            ti += s.x*twi[j] + s.y*twr[j];
        }
        Ts[mi*32 + c] = make_float2(tr, ti);
    }
    __syncthreads();

    // y[a,c] = relu(Re sum_m T[m,c] e^{+i m a 2pi/32})
    for (int idx = tid; idx < 1024; idx += 256) {
        int a = idx >> 5, c = idx & 31;
        float v = 0.f;
        for (int mi = 0; mi < 31; mi++) {
            int j = ((mi+17)*a) & 31;
            float2 t = Ts[mi*32 + c];
            v += t.x*twr[j] - t.y*twi[j];
        }
        ys[idx] = fmaxf(v, 0.f);
    }
    __syncthreads();

    // U[m,c] = sum_a y[a,c] e^{-i m a 2pi/32}, m=0..7
    {
        int m = tid >> 5, c = tid & 31;
        float ur = 0.f, ui = 0.f;
        for (int a = 0; a < 32; a++) {
            int j = (m*a) & 31;
            float y = ys[a*32 + c];
            ur += y*twr[j];
            ui -= y*twi[j];
        }
        Us[tid] = make_float2(ur, ui);
    }
    __syncthreads();

    // V[m,n] = (1/1024) sum_c U[m,c] e^{-i n c 2pi/32}; mirror via conj symmetry
    const float s1 = 1.0f/1024.0f;
    size_t base = ((size_t)k*1024u + (size_t)(b*64+f))*225u;
    for (int idx = tid; idx < 120; idx += 256) {
        int m = idx/15, ni = idx%15, n = ni-7;
        float vr = 0.f, vi = 0.f;
        for (int c = 0; c < 32; c++) {
            int j = ((n+32)*c) & 31;
            float2 u = Us[m*32 + c];
            vr +=  u.x*twr[j] + u.y*twi[j];
            vi += -u.x*twi[j] + u.y*twr[j];
        }
        vr *= s1; vi *= s1;
        g_xf2[base + (m+7)*15 + ni] = make_float2(vr, vi);
        if (m > 0)
            g_xf2[base + (7-m)*15 + (14-ni)] = make_float2(vr, -vi);
    }
}

// ------------------------- Fx2 contraction over k --------------------------
__global__ void __launch_bounds__(256) k_fx2() {
    int bf0 = blockIdx.x * 4;                           // 256 blocks
    __shared__ float2 accs[NP2*4];
    __shared__ float2 tile[4*225];
    __shared__ float  coefs[NP2];
    __shared__ int    mns[NP2];
    int tid = threadIdx.x;
    for (int i = tid; i < NP2*4; i += 256) accs[i] = make_float2(0.f, 0.f);
    for (int i = tid; i < NP2;   i += 256) mns[i]  = g_mnidx[i];
    __syncthreads();
    for (int kk = 0; kk < 32; kk++) {
        for (int i = tid; i < 900; i += 256) {
            int j = i/225, mn = i%225;
            tile[j*225 + mn] = g_xf2[((size_t)kk*1024u + bf0 + j)*225u + mn];
        }
        for (int i = tid; i < NP2; i += 256) coefs[i] = g_cf1[kk*NP2 + i];
        __syncthreads();
        for (int i = tid; i < NP2*4; i += 256) {
            int p2 = i >> 2, j = i & 3;
            float  w = coefs[p2];
            float2 v = tile[j*225 + mns[p2]];
            accs[i].x += w*v.x;
            accs[i].y += w*v.y;
        }
        __syncthreads();
    }
    for (int i = tid; i < NP2*4; i += 256) {
        int p2 = i >> 2, j = i & 3;
        g_Fx2[(size_t)p2*1024u + bf0 + j] = accs[i];
    }
}

// ------------------------- Fy2 (conj) build --------------------------------
__global__ void __launch_bounds__(256) k_fy2(const float* __restrict__ w2) {
    __shared__ float  w2s[1024*9];                      // pitch 9: no conflicts
    __shared__ float2 psis[64];
    int p20 = blockIdx.x * 8;                           // 85 tiles
    int io0 = blockIdx.y * 1024;                        // 8 tiles
    int tid = threadIdx.x;
    float aR[8][4], aI[8][4];
    #pragma unroll
    for (int p = 0; p < 8; p++)
        #pragma unroll
        for (int q = 0; q < 4; q++) { aR[p][q] = 0.f; aI[p][q] = 0.f; }
    for (int gc = 0; gc < 192; gc += 8) {
        for (int i = tid; i < 8192; i += 256) {
            int iol = i >> 3, g = i & 7;
            w2s[iol*9 + g] = w2[(size_t)(io0+iol)*192 + gc + g];
        }
        if (tid < 64) {
            int pj = tid >> 3, g = tid & 7;
            psis[tid] = g_psi3[(p20+pj)*192 + gc + g];
        }
        __syncthreads();
        #pragma unroll
        for (int g = 0; g < 8; g++) {
            float pr[8], pim[8];
            #pragma unroll
            for (int pj = 0; pj < 8; pj++) {
                float2 v = psis[pj*8 + g];
                pr[pj] = v.x; pim[pj] = v.y;
            }
            #pragma unroll
            for (int ioj = 0; ioj < 4; ioj++) {
                float w = w2s[(ioj*256 + tid)*9 + g];
                #pragma unroll
                for (int pj = 0; pj < 8; pj++) {
                    aR[pj][ioj] += w*pr[pj];
                    aI[pj][ioj] += w*pim[pj];
                }
            }
        }
        __syncthreads();
    }
    #pragma unroll
    for (int pj = 0; pj < 8; pj++)
        #pragma unroll
        for (int ioj = 0; ioj < 4; ioj++)
            g_Fy2[(size_t)(p20+pj)*8192u + io0 + ioj*256 + tid] =
                make_float2(aR[pj][ioj], aI[pj][ioj]);
}

// ------------------------- Fz2 batched complex GEMM ------------------------
__global__ void __launch_bounds__(256) k_fz2() {
    int bid = blockIdx.x;                               // 680 (l,m,n) tiles
    int l = 0; while (c_off2[l+1] <= bid) l++;
    int r = bid - c_off2[l], D = 2*l+1;
    int mi = r / D, ni = r % D;
    __shared__ float2 As[256];                          // [b16][ii16]
    __shared__ float2 Bs[2048];                         // [ii16][o128]
    int tid = threadIdx.x;
    int o = tid & 127, bh = tid >> 7;
    float aR[8], aI[8];
    #pragma unroll
    for (int j = 0; j < 8; j++) { aR[j] = 0.f; aI[j] = 0.f; }
    for (int kw = 0; kw < D; kw++) {
        size_t p2A = (size_t)(c_off2[l] + mi*D + kw);
        size_t p2B = (size_t)(c_off2[l] + ni*D + kw);
        for (int ic = 0; ic < 4; ic++) {
            { int bb = tid >> 4, ii = tid & 15;
              As[tid] = g_Fx2[p2A*1024u + bb*64 + ic*16 + ii]; }
            for (int rr = tid; rr < 2048; rr += 256) {
                int ii = rr >> 7, oo = rr & 127;
                Bs[rr] = g_Fy2[p2B*8192u + (ic*16+ii)*128 + oo];
            }
            __syncthreads();
            #pragma unroll 4
            for (int ii = 0; ii < 16; ii++) {
                float2 bv = Bs[ii*128 + o];
                #pragma unroll
                for (int bj = 0; bj < 8; bj++) {
                    float2 av = As[(bh*8+bj)*16 + ii];
                    aR[bj] += av.x*bv.x - av.y*bv.y;
                    aI[bj] += av.x*bv.y + av.y*bv.x;
                }
            }
            __syncthreads();
        }
    }
    #pragma unroll
    for (int bj = 0; bj < 8; bj++) {
        int bb = bh*8 + bj;
        g_Fz2[(size_t)(bb*128 + o)*NP2 + bid] = make_float2(aR[bj], aI[bj]);
    }
}

// ------------------------- final fused iSO3 + relu + mean ------------------
__global__ void __launch_bounds__(256) k_final() {
    int bo = blockIdx.x;                                // 2048
    __shared__ float2 Fzs[NP2];
    __shared__ float  d2s[NP2];
    __shared__ float2 Ss[240];
    __shared__ float2 Ts[240];
    __shared__ float  twr[16], twi[16], red[256];
    int tid = threadIdx.x;
    for (int i = tid; i < NP2; i += 256) Fzs[i] = g_Fz2[(size_t)bo*NP2 + i];
    if (tid < 16) {
        float s, c; sincosf((float)tid*(float)(2.0*PI_D/16.0), &s, &c);
        twr[tid] = c; twi[tid] = s;                     // e^{+2pi i j/16}
    }
    float accum = 0.f;
    for (int k2 = 0; k2 < 16; k2++) {
        for (int i = tid; i < NP2; i += 256) d2s[i] = g_dL2[k2*NP2 + i];
        __syncthreads();
        if (tid < 225) {
            int mi = tid/15, ni = tid%15, m = mi-7, n = ni-7;
            int am = m < 0 ? -m : m, an = n < 0 ? -n : n;
            int lmin = am > an ? am : an;
            float sr = 0.f, si = 0.f;
            for (int l = lmin; l < 8; l++) {
                int D = 2*l+1;
                int p = c_off2[l] + (m+l)*D + (n+l);
                float w = (float)D * d2s[p];
                float2 fz = Fzs[p];
                sr += w*fz.x; si += w*fz.y;
            }
            Ss[mi*16 + ni] = make_float2(sr, si);
        }
        __syncthreads();
        if (tid < 240) {
            int mi = tid >> 4, c = tid & 15;
            float tr = 0.f, ti = 0.f;
            for (int ni = 0; ni < 15; ni++) {
                int j = ((ni+9)*c) & 15;
                float2 s = Ss[mi*16 + ni];
                tr += s.x*twr[j] - s.y*twi[j];
                ti += s.x*twi[j] + s.y*twr[j];
            }
            Ts[mi*16 + c] = make_float2(tr, ti);
        }
        __syncthreads();
        {
            int a = tid >> 4, c = tid & 15;
            float v = 0.f;
            for (int mi = 0; mi < 15; mi++) {
                int j = ((mi+9)*a) & 15;
                float2 t = Ts[mi*16 + c];
                v += t.x*twr[j] - t.y*twi[j];
            }
            accum += fmaxf(v, 0.f) * g_Wl2[k2];
        }
        __syncthreads();
    }
    red[tid] = accum * (1.0f/256.0f);
    __syncthreads();
    for (int s = 128; s > 0; s >>= 1) {
        if (tid < s) red[tid] += red[tid + s];
        __syncthreads();
    }
    if (tid == 0) g_feat[bo] = red[0];
}

// ------------------------- linear head -------------------------------------
__global__ void k_head(const float* __restrict__ lw,
                       const float* __restrict__ lb,
                       float* __restrict__ out) {
    int t = threadIdx.x;
    if (t < 160) {
        int b = t / 10, j = t % 10;
        float s = lb[j];
        for (int o = 0; o < 128; o++)
            s += g_feat[b*128 + o] * lw[j*128 + o];
        out[t] = s;
    }
}

// ------------------------- launcher ----------------------------------------
extern "C" void kernel_launch(void* const* d_in, const int* in_sizes, int n_in,
                              void* d_out, int out_size) {
    const float* x  = (const float*)d_in[0];
    const float* w1 = (const float*)d_in[1];
    const float* w2 = (const float*)d_in[2];
    const float* lw = (const float*)d_in[3];
    const float* lb = (const float*)d_in[4];
    float* out = (float*)d_out;

    k_tables<<<917, 256>>>();          // 234608 wigner-d entries
    k_weights<<<1, 192>>>();
    k_prep<<<85, 256>>>();
    k_psi3gen<<<510, 256>>>();

    k_dft1<<<2048, 64>>>(x);
    k_fx<<<16, 256>>>();
    k_fyc<<<64, 256>>>(w1);
    k_mid<<<32768, 256>>>();
    k_fx2<<<256, 256>>>();
    k_fy2<<<dim3(85, 8), 256>>>(w2);
    k_fz2<<<680, 256>>>();
    k_final<<<2048, 256>>>();
    k_head<<<1, 192>>>(lw, lb, out);
}

// round 13
// speedup vs baseline: 1.3598x; 1.3598x over previous
#include <cuda_runtime.h>
#include <cuda_bf16.h>
#include <math.h>

// ============================================================================
// S2ConvNet forward on GB300.
//   x(16,1,128,128) f32 -> out(16,10) f32
//   B_IN=64, B_L1=16, B_L2=8, F1=64, F2=128, BATCH=16
// R11: conjugate-symmetry fold (m>=0 only) + register twiddle recurrences in
// the two fused SO(3) stages (k_mid, k_final) -> cuts smem crossbar traffic.
// ============================================================================

#define PI_D 3.14159265358979323846

#define NP1   256      // sum_{l<16}(2l+1)
#define NP2F  5456     // sum_{l<16}(2l+1)^2
#define NP2   680      // sum_{l<8}(2l+1)^2
#define NH1   2856     // sum_{l<16}(l+1)(2l+1)
#define NH2   372      // sum_{l<8}(l+1)(2l+1)
#define BF    1024     // BATCH*F1
#define BO    2048     // BATCH*F2

__constant__ int c_off2[17] = {0,1,10,35,84,165,286,455,680,969,1330,1771,
                               2300,2925,3654,4495,5456};
__constant__ int c_choff[17] = {0,1,7,22,50,95,161,252,372,525,715,946,
                                1222,1547,1925,2360,2856};

// ------------------------- device global scratch ---------------------------
__device__ float  g_Win[128];
__device__ float  g_Wl1[32];
__device__ float  g_Wl2[16];
__device__ float  g_dcol[256*128];          // [p1][k]  d^l_{m0}(beta_in_k)
__device__ float  g_dL1[32*NP2F];           // [k][p2f] full d, L1 betas
__device__ float  g_dL2[16*NP2];            // [k][p2]  full d, L2 betas
__device__ float  g_dG[3*NP2F];             // [gbeta][p2f] full d, grid betas
__device__ __align__(16) float g_dL1h[32*NH1];  // folded: (2l+1)*(m>0?2:1)*d
__device__ __align__(16) float g_dL2h[16*NH2];
__device__ float  g_cf1[32*NP2];            // 2pi*Wl1[k]*dL1 (l<8)
__device__ int    g_mnidx[NP2];             // p2 -> (m+7)*15+(n+7)
__device__ float2 g_psi3[NP2*192];          // conj(psi_SO3)
__device__ float2 g_xf1[31*2048];           // [m+15][b*128+k]
__device__ float2 g_Fx[16*256];             // [b][p1]
__device__ float2 g_FyC[64*256];            // [o][p1]  (conj applied)
__device__ float2 g_xf2[32u*1024u*225u];    // [k][bf][mn]  (59 MB)
__device__ float2 g_Fx2[NP2*BF];            // [p2][bf]
__device__ float2 g_Fy2[NP2*8192];          // [p2][i*128+o] (conj applied)
__device__ float2 g_Fz2[BO*NP2];            // [b*128+o][p2]
__device__ float  g_feat[BO];

// ------------------------- Wigner small-d (fp64) ---------------------------
__device__ double wigd(int l, int m, int n, double beta) {
    double fact[32];
    fact[0] = 1.0;
    for (int i = 1; i < 32; i++) fact[i] = fact[i-1] * (double)i;
    double ch = cos(0.5*beta), sh = sin(0.5*beta);
    int smin = n - m; if (smin < 0) smin = 0;
    int smax = l + n; if (l - m < smax) smax = l - m;
    double pref = sqrt(fact[l+m]*fact[l-m]*fact[l+n]*fact[l-n]);
    double sum = 0.0;
    for (int s = smin; s <= smax; s++) {
        int ae = 2*l + n - m - 2*s;
        int be = m - n + 2*s;
        double pc = 1.0; for (int i = 0; i < ae; i++) pc *= ch;
        double ps = 1.0; for (int i = 0; i < be; i++) ps *= sh;
        double t = pref/(fact[l+n-s]*fact[s]*fact[m-n+s]*fact[l-m-s])*pc*ps;
        sum += ((m-n+s)&1) ? -t : t;
    }
    return sum;
}

__device__ __forceinline__ void dec_p2(int p, int* lo, int* mo, int* no) {
    int l = 0;
    while (c_off2[l+1] <= p) l++;
    int r = p - c_off2[l], D = 2*l+1;
    *lo = l; *mo = r/D - l; *no = r%D - l;
}

// ------------------------- table generation --------------------------------
__global__ void k_tables() {
    int id = blockIdx.x*blockDim.x + threadIdx.x;
    if (id < 32768) {                                   // g_dcol
        int p1 = id >> 7, k = id & 127;
        int l = 0; while ((l+1)*(l+1) <= p1) l++;
        int m = p1 - l*l - l;
        g_dcol[id] = (float)wigd(l, m, 0, PI_D*(2*k+1)/256.0);
        return;
    }
    id -= 32768;
    if (id < 32*NP2F) {                                 // g_dL1
        int k = id / NP2F, p = id % NP2F;
        int l, m, n; dec_p2(p, &l, &m, &n);
        g_dL1[id] = (float)wigd(l, m, n, PI_D*(2*k+1)/64.0);
        return;
    }
    id -= 32*NP2F;
    if (id < 16*NP2) {                                  // g_dL2
        int k = id / NP2, p = id % NP2;
        int l, m, n; dec_p2(p, &l, &m, &n);
        g_dL2[id] = (float)wigd(l, m, n, PI_D*(2*k+1)/32.0);
        return;
    }
    id -= 16*NP2;
    if (id < 3*NP2F) {                                  // g_dG
        int gi = id / NP2F, p = id % NP2F;
        int l, m, n; dec_p2(p, &l, &m, &n);
        g_dG[id] = (float)wigd(l, m, n, (gi+1)*PI_D/24.0);
    }
}

// folded half-tables for the symmetric fused stages
__global__ void k_fold() {
    int id = blockIdx.x*256 + threadIdx.x;
    if (id < 32*NH1) {
        int k = id / NH1, j = id % NH1;
        int l = 0; while (c_choff[l+1] <= j) l++;
        int r = j - c_choff[l], D = 2*l+1;
        int m = r / D, nn = r % D;
        float v = g_dL1[k*NP2F + c_off2[l] + (m+l)*D + nn];
        g_dL1h[id] = (float)D * (m > 0 ? 2.f : 1.f) * v;
        return;
    }
    id -= 32*NH1;
    if (id < 16*NH2) {
        int k = id / NH2, j = id % NH2;
        int l = 0; while (c_choff[l+1] <= j) l++;
        int r = j - c_choff[l], D = 2*l+1;
        int m = r / D, nn = r % D;
        float v = g_dL2[k*NP2 + c_off2[l] + (m+l)*D + nn];
        g_dL2h[id] = (float)D * (m > 0 ? 2.f : 1.f) * v;
    }
}

__global__ void k_weights() {
    int id = threadIdx.x;
    int b, j; float* dst;
    if (id < 128)      { b = 64; j = id;       dst = &g_Win[j]; }
    else if (id < 160) { b = 16; j = id - 128; dst = &g_Wl1[j]; }
    else if (id < 176) { b = 8;  j = id - 160; dst = &g_Wl2[j]; }
    else return;
    double s = 0.0;
    for (int l2 = 0; l2 < b; l2++)
        s += sin((2.0*j+1)*(2.0*l2+1)*PI_D/(4.0*b)) / (2.0*l2+1);
    *dst = (float)((2.0/b)*sin(PI_D*(2*j+1)/(4.0*b))*s);
}

__global__ void k_prep() {
    int id = blockIdx.x*256 + threadIdx.x;              // 32*680 = 21760
    if (id < 32*NP2) {
        int k = id / NP2, p = id % NP2;
        g_cf1[id] = (float)(2.0*PI_D) * g_Wl1[k] * g_dL1[k*NP2F + p];
    }
    if (id < NP2) {
        int l, m, n; dec_p2(id, &l, &m, &n);
        g_mnidx[id] = (m+7)*15 + (n+7);
    }
}

__global__ void k_psi3gen() {
    int id = blockIdx.x*256 + threadIdx.x;              // 680*192
    if (id >= NP2*192) return;
    int p2 = id / 192, g = id % 192;
    int l, m, n; dec_p2(p2, &l, &m, &n);
    int ia = (g>>3)&7, ic = g&7, ib = g>>6;
    float d = g_dG[ib*NP2F + p2];
    int ph = ((m-n)*ia + n*ic + 160) & 7;               // conj: e^{+i(m a + n g)}
    float s, c; sincosf((float)ph * (float)(PI_D/4.0), &s, &c);
    g_psi3[id] = make_float2(d*c, d*s);
}

// ------------------------- S2 stage ----------------------------------------
__global__ void k_dft1(const float* __restrict__ x) {
    int bid = blockIdx.x;                               // b*128 + k
    __shared__ float xs[128], tcr[128], tci[128];
    int tid = threadIdx.x;                              // 64
    xs[tid]      = x[bid*128 + tid];
    xs[tid+64]   = x[bid*128 + tid + 64];
    float s, c;
    sincosf((float)tid      * (float)(-2.0*PI_D/128.0), &s, &c); tcr[tid]=c;    tci[tid]=s;
    sincosf((float)(tid+64) * (float)(-2.0*PI_D/128.0), &s, &c); tcr[tid+64]=c; tci[tid+64]=s;
    __syncthreads();
    if (tid < 31) {
        int m = tid - 15;
        float ar = 0.f, ai = 0.f;
        for (int a = 0; a < 128; a++) {
            int j = ((m+128)*a) & 127;
            ar += xs[a]*tcr[j];
            ai += xs[a]*tci[j];
        }
        g_xf1[tid*2048 + bid] = make_float2(ar, ai);
    }
}

__global__ void k_fx() {
    int id = blockIdx.x*256 + threadIdx.x;              // 4096
    if (id >= 4096) return;
    int b = id & 15, p1 = id >> 4;
    int l = 0; while ((l+1)*(l+1) <= p1) l++;
    int m = p1 - l*l - l;
    float sr = 0.f, si = 0.f;
    for (int kk = 0; kk < 128; kk++) {
        float w = g_Win[kk]*g_dcol[p1*128 + kk];
        float2 v = g_xf1[(m+15)*2048 + b*128 + kk];
        sr += w*v.x; si += w*v.y;
    }
    float sc = (float)(2.0*PI_D/128.0);
    g_Fx[b*256 + p1] = make_float2(sr*sc, si*sc);
}

__global__ void k_fyc(const float* __restrict__ w1) {
    int id = blockIdx.x*256 + threadIdx.x;              // 16384
    if (id >= 16384) return;
    int p1 = id >> 6, o = id & 63;
    int l = 0; while ((l+1)*(l+1) <= p1) l++;
    int m = p1 - l*l - l;
    int dbase = c_off2[l] + (m+l)*(2*l+1) + l;          // column n=0
    float sr = 0.f, si = 0.f;
    for (int g = 0; g < 24; g++) {
        int ib = g >> 3, ia = g & 7;
        float d = g_dG[ib*NP2F + dbase];
        int ph = (m*ia + 120) & 7;                      // conj: e^{+i m a}
        float sn, cs; sincosf((float)ph*(float)(PI_D/4.0), &sn, &cs);
        float wv = w1[o*24 + g];
        sr += wv*d*cs;
        si += wv*d*sn;
    }
    g_FyC[o*256 + p1] = make_float2(sr, si);
}

// ------------------------- fused middle stage ------------------------------
// per (b,f,k): S(m>=0) -> R over m (16 terms) -> y=relu(Re DFT_n) -> fwd DFT
__global__ void __launch_bounds__(256) k_mid() {
    int bid = blockIdx.x;                               // 32768
    int k = bid & 31, f = (bid>>5)&63, b = bid>>11;
    __shared__ float  ds[NH1];
    __shared__ float2 fxs[256], fycs[256];
    __shared__ float2 Ss[16*31];                        // [m][ni]  (m>0 doubled)
    __shared__ float2 Rs[32*31];                        // [a][ni]
    __shared__ float  ys[1024];                         // [a][c]
    __shared__ float2 Us[8*32];
    __shared__ float2 tws[32];                          // e^{+2pi i j/32}
    int tid = threadIdx.x;

    {
        const float4* src = (const float4*)(g_dL1h + k*NH1);
        float4* dst = (float4*)ds;
        for (int i = tid; i < NH1/4; i += 256) dst[i] = src[i];
    }
    fxs[tid]  = g_Fx[b*256 + tid];
    fycs[tid] = g_FyC[f*256 + tid];
    if (tid < 32) {
        float s, c; sincosf((float)tid*(float)(2.0*PI_D/32.0), &s, &c);
        tws[tid] = make_float2(c, s);
    }
    __syncthreads();

    // S[m,ni] = sum_l wfold * Fx[l,m] FyC[l,n],  m=0..15, n=ni-15
    for (int idx = tid; idx < 496; idx += 256) {
        int mi = idx / 31, ni = idx - mi*31;
        int n = ni - 15;
        int an = n < 0 ? -n : n;
        int lmin = mi > an ? mi : an;
        int ch = (lmin*(lmin+1)*(4*lmin-1))/6;
        int q  = lmin*lmin + lmin;
        float sr = 0.f, si = 0.f;
        for (int l = lmin; l < 16; l++) {
            int D = 2*l+1;
            float w   = ds[ch + mi*D + n + l];
            float2 av = fxs[q + mi];
            float2 bv = fycs[q + n];
            sr += w*(av.x*bv.x - av.y*bv.y);
            si += w*(av.x*bv.y + av.y*bv.x);
            ch += (l+1)*D;
            q  += 2*l + 2;
        }
        Ss[idx] = make_float2(sr, si);
    }
    __syncthreads();

    // R[a,ni] = sum_{m=0..15} Ss[m,ni] e^{+i m a 2pi/32}  (register twiddle)
    {
        int a = tid & 31, nbase = (tid >> 5) * 4;
        float2 step = tws[a];
        float2 w = make_float2(1.f, 0.f);
        float2 acc0 = {0,0}, acc1 = {0,0}, acc2 = {0,0}, acc3 = {0,0};
        bool full = (nbase + 3 < 31);
        for (int m = 0; m < 16; m++) {
            float2 s0 = Ss[m*31 + nbase];
            float2 s1 = Ss[m*31 + nbase + 1];
            float2 s2 = Ss[m*31 + nbase + 2];
            acc0.x += s0.x*w.x - s0.y*w.y;  acc0.y += s0.x*w.y + s0.y*w.x;
            acc1.x += s1.x*w.x - s1.y*w.y;  acc1.y += s1.x*w.y + s1.y*w.x;
            acc2.x += s2.x*w.x - s2.y*w.y;  acc2.y += s2.x*w.y + s2.y*w.x;
            if (full) {
                float2 s3 = Ss[m*31 + nbase + 3];
                acc3.x += s3.x*w.x - s3.y*w.y;  acc3.y += s3.x*w.y + s3.y*w.x;
            }
            float nr = w.x*step.x - w.y*step.y;
            w.y = w.x*step.y + w.y*step.x;
            w.x = nr;
        }
        Rs[a*31 + nbase]     = acc0;
        Rs[a*31 + nbase + 1] = acc1;
        Rs[a*31 + nbase + 2] = acc2;
        if (full) Rs[a*31 + nbase + 3] = acc3;
    }
    __syncthreads();

    // y[a,c] = relu( Re sum_{ni} Rs[a,ni] e^{+i (ni-15) c 2pi/32} )
    {
        int c = tid & 31, a0 = tid >> 5;
        float2 step = tws[c];
        float2 w0 = tws[(17*c) & 31];                   // e^{-i 15 c}
        #pragma unroll
        for (int pass = 0; pass < 4; pass++) {
            int a = a0 + pass*8;
            float2 w = w0;
            float v = 0.f;
            for (int ni = 0; ni < 31; ni++) {
                float2 r = Rs[a*31 + ni];
                v += r.x*w.x - r.y*w.y;
                float nr = w.x*step.x - w.y*step.y;
                w.y = w.x*step.y + w.y*step.x;
                w.x = nr;
            }
            ys[a*32 + c] = fmaxf(v, 0.f);
        }
    }
    __syncthreads();

    // U[m,c] = sum_a y[a,c] e^{-i m a 2pi/32}, m=0..7
    {
        int m = tid >> 5, c = tid & 31;
        float2 st = tws[m]; st.y = -st.y;               // e^{-i m}
        float2 w = make_float2(1.f, 0.f);
        float ur = 0.f, ui = 0.f;
        for (int a = 0; a < 32; a++) {
            float y = ys[a*32 + c];
            ur += y*w.x; ui += y*w.y;
            float nr = w.x*st.x - w.y*st.y;
            w.y = w.x*st.y + w.y*st.x;
            w.x = nr;
        }
        Us[tid] = make_float2(ur, ui);
    }
    __syncthreads();

    // V[m,n] = (1/1024) sum_c U[m,c] e^{-i n c 2pi/32}; mirror via conj symmetry
    const float s1 = 1.0f/1024.0f;
    size_t base = ((size_t)k*1024u + (size_t)(b*64+f))*225u;
    for (int idx = tid; idx < 120; idx += 256) {
        int m = idx/15, ni = idx%15, n = ni-7;
        float vr = 0.f, vi = 0.f;
        for (int c = 0; c < 32; c++) {
            int j = ((n+32)*c) & 31;
            float2 u = Us[m*32 + c];
            float2 t = tws[j];
            vr +=  u.x*t.x + u.y*t.y;
            vi += -u.x*t.y + u.y*t.x;
        }
        vr *= s1; vi *= s1;
        g_xf2[base + (m+7)*15 + ni] = make_float2(vr, vi);
        if (m > 0)
            g_xf2[base + (7-m)*15 + (14-ni)] = make_float2(vr, -vi);
    }
}

// ------------------------- Fx2 contraction over k --------------------------
__global__ void __launch_bounds__(256) k_fx2() {
    int bf0 = blockIdx.x * 4;                           // 256 blocks
    __shared__ float2 accs[NP2*4];
    __shared__ float2 tile[4*225];
    __shared__ float  coefs[NP2];
    __shared__ int    mns[NP2];
    int tid = threadIdx.x;
    for (int i = tid; i < NP2*4; i += 256) accs[i] = make_float2(0.f, 0.f);
    for (int i = tid; i < NP2;   i += 256) mns[i]  = g_mnidx[i];
    __syncthreads();
    for (int kk = 0; kk < 32; kk++) {
        for (int i = tid; i < 900; i += 256) {
            int j = i/225, mn = i%225;
            tile[j*225 + mn] = g_xf2[((size_t)kk*1024u + bf0 + j)*225u + mn];
        }
        for (int i = tid; i < NP2; i += 256) coefs[i] = g_cf1[kk*NP2 + i];
        __syncthreads();
        for (int i = tid; i < NP2*4; i += 256) {
            int p2 = i >> 2, j = i & 3;
            float  w = coefs[p2];
            float2 v = tile[j*225 + mns[p2]];
            accs[i].x += w*v.x;
            accs[i].y += w*v.y;
        }
        __syncthreads();
    }
    for (int i = tid; i < NP2*4; i += 256) {
        int p2 = i >> 2, j = i & 3;
        g_Fx2[(size_t)p2*1024u + bf0 + j] = accs[i];
    }
}

// ------------------------- Fy2 (conj) build --------------------------------
__global__ void __launch_bounds__(256) k_fy2(const float* __restrict__ w2) {
    __shared__ float  w2s[1024*9];
    __shared__ float2 psis[64];
    int p20 = blockIdx.x * 8;                           // 85 tiles
    int io0 = blockIdx.y * 1024;                        // 8 tiles
    int tid = threadIdx.x;
    float aR[8][4], aI[8][4];
    #pragma unroll
    for (int p = 0; p < 8; p++)
        #pragma unroll
        for (int q = 0; q < 4; q++) { aR[p][q] = 0.f; aI[p][q] = 0.f; }
    for (int gc = 0; gc < 192; gc += 8) {
        for (int i = tid; i < 8192; i += 256) {
            int iol = i >> 3, g = i & 7;
            w2s[iol*9 + g] = w2[(size_t)(io0+iol)*192 + gc + g];
        }
        if (tid < 64) {
            int pj = tid >> 3, g = tid & 7;
            psis[tid] = g_psi3[(p20+pj)*192 + gc + g];
        }
        __syncthreads();
        #pragma unroll
        for (int g = 0; g < 8; g++) {
            float pr[8], pim[8];
            #pragma unroll
            for (int pj = 0; pj < 8; pj++) {
                float2 v = psis[pj*8 + g];
                pr[pj] = v.x; pim[pj] = v.y;
            }
            #pragma unroll
            for (int ioj = 0; ioj < 4; ioj++) {
                float w = w2s[(ioj*256 + tid)*9 + g];
                #pragma unroll
                for (int pj = 0; pj < 8; pj++) {
                    aR[pj][ioj] += w*pr[pj];
                    aI[pj][ioj] += w*pim[pj];
                }
            }
        }
        __syncthreads();
    }
    #pragma unroll
    for (int pj = 0; pj < 8; pj++)
        #pragma unroll
        for (int ioj = 0; ioj < 4; ioj++)
            g_Fy2[(size_t)(p20+pj)*8192u + io0 + ioj*256 + tid] =
                make_float2(aR[pj][ioj], aI[pj][ioj]);
}

// ------------------------- Fz2 batched complex GEMM ------------------------
__global__ void __launch_bounds__(256) k_fz2() {
    int bid = blockIdx.x;                               // 680 (l,m,n) tiles
    int l = 0; while (c_off2[l+1] <= bid) l++;
    int r = bid - c_off2[l], D = 2*l+1;
    int mi = r / D, ni = r % D;
    __shared__ float2 As[256];                          // [b16][ii16]
    __shared__ float2 Bs[2048];                         // [ii16][o128]
    int tid = threadIdx.x;
    int o = tid & 127, bh = tid >> 7;
    float aR[8], aI[8];
    #pragma unroll
    for (int j = 0; j < 8; j++) { aR[j] = 0.f; aI[j] = 0.f; }
    for (int kw = 0; kw < D; kw++) {
        size_t p2A = (size_t)(c_off2[l] + mi*D + kw);
        size_t p2B = (size_t)(c_off2[l] + ni*D + kw);
        for (int ic = 0; ic < 4; ic++) {
            { int bb = tid >> 4, ii = tid & 15;
              As[tid] = g_Fx2[p2A*1024u + bb*64 + ic*16 + ii]; }
            for (int rr = tid; rr < 2048; rr += 256) {
                int ii = rr >> 7, oo = rr & 127;
                Bs[rr] = g_Fy2[p2B*8192u + (ic*16+ii)*128 + oo];
            }
            __syncthreads();
            #pragma unroll 4
            for (int ii = 0; ii < 16; ii++) {
                float2 bv = Bs[ii*128 + o];
                #pragma unroll
                for (int bj = 0; bj < 8; bj++) {
                    float2 av = As[(bh*8+bj)*16 + ii];
                    aR[bj] += av.x*bv.x - av.y*bv.y;
                    aI[bj] += av.x*bv.y + av.y*bv.x;
                }
            }
            __syncthreads();
        }
    }
    #pragma unroll
    for (int bj = 0; bj < 8; bj++) {
        int bb = bh*8 + bj;
        g_Fz2[(size_t)(bb*128 + o)*NP2 + bid] = make_float2(aR[bj], aI[bj]);
    }
}

// ------------------------- final fused iSO3 + relu + mean ------------------
__global__ void __launch_bounds__(256) k_final() {
    int bo = blockIdx.x;                                // 2048
    __shared__ float2 Fzs[NP2];
    __shared__ float  d2s[NH2];
    __shared__ float2 Ss[8*15];
    __shared__ float2 Rs[16*15];
    __shared__ float2 tws[16];
    __shared__ float  red[256];
    int tid = threadIdx.x;
    for (int i = tid; i < NP2; i += 256) Fzs[i] = g_Fz2[(size_t)bo*NP2 + i];
    if (tid < 16) {
        float s, c; sincosf((float)tid*(float)(2.0*PI_D/16.0), &s, &c);
        tws[tid] = make_float2(c, s);                   // e^{+2pi i j/16}
    }
    float accum = 0.f;
    for (int k2 = 0; k2 < 16; k2++) {
        for (int i = tid; i < NH2; i += 256) d2s[i] = g_dL2h[k2*NH2 + i];
        __syncthreads();
        // S: m=0..7, ni=0..14 (folded weights)
        if (tid < 120) {
            int mi = tid/15, ni = tid%15, n = ni-7;
            int an = n < 0 ? -n : n;
            int lmin = mi > an ? mi : an;
            int ch = (lmin*(lmin+1)*(4*lmin-1))/6;
            int co = (4*lmin*lmin*lmin - lmin)/3;
            float sr = 0.f, si = 0.f;
            for (int l = lmin; l < 8; l++) {
                int D = 2*l+1;
                float w = d2s[ch + mi*D + n + l];
                float2 fz = Fzs[co + (mi+l)*D + (n+l)];
                sr += w*fz.x; si += w*fz.y;
                ch += (l+1)*D;
                co += D*D;
            }
            Ss[mi*15 + ni] = make_float2(sr, si);
        }
        __syncthreads();
        // R[a,ni] = sum_m Ss[m,ni] e^{+i m a 2pi/16}
        if (tid < 240) {
            int a = tid & 15, ni = tid >> 4;
            float2 step = tws[a];
            float2 w = make_float2(1.f, 0.f);
            float2 acc = {0,0};
            for (int m = 0; m < 8; m++) {
                float2 s = Ss[m*15 + ni];
                acc.x += s.x*w.x - s.y*w.y;
                acc.y += s.x*w.y + s.y*w.x;
                float nr = w.x*step.x - w.y*step.y;
                w.y = w.x*step.y + w.y*step.x;
                w.x = nr;
            }
            Rs[a*15 + ni] = acc;
        }
        __syncthreads();
        // y[a,c] = Re sum_ni Rs[a,ni] e^{+i (ni-7) c 2pi/16}
        {
            int a = tid >> 4, c = tid & 15;
            float2 step = tws[c];
            float2 w = tws[(9*c) & 15];                 // e^{-i 7 c}
            float v = 0.f;
            for (int ni = 0; ni < 15; ni++) {
                float2 r = Rs[a*15 + ni];
                v += r.x*w.x - r.y*w.y;
                float nr = w.x*step.x - w.y*step.y;
                w.y = w.x*step.y + w.y*step.x;
                w.x = nr;
            }
            accum += fmaxf(v, 0.f) * g_Wl2[k2];
        }
        __syncthreads();
    }
    red[tid] = accum * (1.0f/256.0f);
    __syncthreads();
    for (int s = 128; s > 0; s >>= 1) {
        if (tid < s) red[tid] += red[tid + s];
        __syncthreads();
    }
    if (tid == 0) g_feat[bo] = red[0];
}

// ------------------------- linear head -------------------------------------
__global__ void k_head(const float* __restrict__ lw,
                       const float* __restrict__ lb,
                       float* __restrict__ out) {
    int t = threadIdx.x;
    if (t < 160) {
        int b = t / 10, j = t % 10;
        float s = lb[j];
        for (int o = 0; o < 128; o++)
            s += g_feat[b*128 + o] * lw[j*128 + o];
        out[t] = s;
    }
}

// ------------------------- launcher ----------------------------------------
extern "C" void kernel_launch(void* const* d_in, const int* in_sizes, int n_in,
                              void* d_out, int out_size) {
    const float* x  = (const float*)d_in[0];
    const float* w1 = (const float*)d_in[1];
    const float* w2 = (const float*)d_in[2];
    const float* lw = (const float*)d_in[3];
    const float* lb = (const float*)d_in[4];
    float* out = (float*)d_out;

    k_tables<<<917, 256>>>();
    k_fold<<<381, 256>>>();
    k_weights<<<1, 192>>>();
    k_prep<<<85, 256>>>();
    k_psi3gen<<<510, 256>>>();

    k_dft1<<<2048, 64>>>(x);
    k_fx<<<16, 256>>>();
    k_fyc<<<64, 256>>>(w1);
    k_mid<<<32768, 256>>>();
    k_fx2<<<256, 256>>>();
    k_fy2<<<dim3(85, 8), 256>>>(w2);
    k_fz2<<<680, 256>>>();
    k_final<<<2048, 256>>>();
    k_head<<<1, 192>>>(lw, lb, out);
}

// round 15
// speedup vs baseline: 1.4471x; 1.0642x over previous
#include <cuda_runtime.h>
#include <cuda_bf16.h>
#include <math.h>

// ============================================================================
// S2ConvNet forward on GB300.
//   x(16,1,128,128) f32 -> out(16,10) f32
// R13: k_mid twiddle hoist + pair-folding (y/U stages), k_fz2 split-k
// balancing, tables folded inline, launch order puts k_mid 6th for ncu.
// R14: identical resubmit (previous bench failed on container infra).
// ============================================================================

#define PI_D 3.14159265358979323846

#define NP1   256      // sum_{l<16}(2l+1)
#define NP2F  5456     // sum_{l<16}(2l+1)^2
#define NP2   680      // sum_{l<8}(2l+1)^2
#define NH1   2856     // sum_{l<16}(l+1)(2l+1)
#define NH2   372      // sum_{l<8}(l+1)(2l+1)
#define BF    1024     // BATCH*F1
#define BO    2048     // BATCH*F2

__constant__ int c_off2[17] = {0,1,10,35,84,165,286,455,680,969,1330,1771,
                               2300,2925,3654,4495,5456};
__constant__ int c_choff[17] = {0,1,7,22,50,95,161,252,372,525,715,946,
                                1222,1547,1925,2360,2856};

// ------------------------- device global scratch ---------------------------
__device__ float  g_Win[128];
__device__ float  g_Wl1[32];
__device__ float  g_Wl2[16];
__device__ float  g_dcol[256*128];          // [p1][k]  d^l_{m0}(beta_in_k)
__device__ float  g_dL1[32*NP2F];           // [k][p2f] full d, L1 betas
__device__ float  g_dL2[16*NP2];            // [k][p2]  full d, L2 betas
__device__ float  g_dG[3*NP2F];             // [gbeta][p2f] full d, grid betas
__device__ __align__(16) float g_dL1h[32*NH1];  // folded: (2l+1)*(m>0?2:1)*d
__device__ __align__(16) float g_dL2h[16*NH2];
__device__ float  g_cf1[32*NP2];            // 2pi*Wl1[k]*dL1 (l<8)
__device__ int    g_mnidx[NP2];             // p2 -> (m+7)*15+(n+7)
__device__ float2 g_psi3[NP2*192];          // conj(psi_SO3)
__device__ float2 g_xf1[31*2048];           // [m+15][b*128+k]
__device__ float2 g_Fx[16*256];             // [b][p1]
__device__ float2 g_FyC[64*256];            // [o][p1]  (conj applied)
__device__ float2 g_xf2[32u*1024u*225u];    // [k][bf][mn]  (59 MB)
__device__ float2 g_Fx2[NP2*BF];            // [p2][bf]
__device__ float2 g_Fy2[NP2*8192];          // [p2][i*128+o] (conj applied)
__device__ float2 g_Fz2[BO*NP2];            // [b*128+o][p2]  (kw half 0)
__device__ float2 g_Fz2b[BO*NP2];           // [b*128+o][p2]  (kw half 1)
__device__ float  g_feat[BO];

// ------------------------- Wigner small-d (fp64) ---------------------------
__device__ double wigd(int l, int m, int n, double beta) {
    double fact[32];
    fact[0] = 1.0;
    for (int i = 1; i < 32; i++) fact[i] = fact[i-1] * (double)i;
    double ch = cos(0.5*beta), sh = sin(0.5*beta);
    int smin = n - m; if (smin < 0) smin = 0;
    int smax = l + n; if (l - m < smax) smax = l - m;
    double pref = sqrt(fact[l+m]*fact[l-m]*fact[l+n]*fact[l-n]);
    double sum = 0.0;
    for (int s = smin; s <= smax; s++) {
        int ae = 2*l + n - m - 2*s;
        int be = m - n + 2*s;
        double pc = 1.0; for (int i = 0; i < ae; i++) pc *= ch;
        double ps = 1.0; for (int i = 0; i < be; i++) ps *= sh;
        double t = pref/(fact[l+n-s]*fact[s]*fact[m-n+s]*fact[l-m-s])*pc*ps;
        sum += ((m-n+s)&1) ? -t : t;
    }
    return sum;
}

__device__ __forceinline__ void dec_p2(int p, int* lo, int* mo, int* no) {
    int l = 0;
    while (c_off2[l+1] <= p) l++;
    int r = p - c_off2[l], D = 2*l+1;
    *lo = l; *mo = r/D - l; *no = r%D - l;
}

// ------------------------- table generation --------------------------------
__global__ void k_tables() {
    int id = blockIdx.x*blockDim.x + threadIdx.x;
    if (id < 32768) {                                   // g_dcol
        int p1 = id >> 7, k = id & 127;
        int l = 0; while ((l+1)*(l+1) <= p1) l++;
        int m = p1 - l*l - l;
        g_dcol[id] = (float)wigd(l, m, 0, PI_D*(2*k+1)/256.0);
        return;
    }
    id -= 32768;
    if (id < 32*NP2F) {                                 // g_dL1 (+ folded half)
        int k = id / NP2F, p = id % NP2F;
        int l, m, n; dec_p2(p, &l, &m, &n);
        float v = (float)wigd(l, m, n, PI_D*(2*k+1)/64.0);
        g_dL1[id] = v;
        if (m >= 0)
            g_dL1h[k*NH1 + c_choff[l] + m*(2*l+1) + (n+l)] =
                (float)(2*l+1) * (m > 0 ? 2.f : 1.f) * v;
        return;
    }
    id -= 32*NP2F;
    if (id < 16*NP2) {                                  // g_dL2 (+ folded half)
        int k = id / NP2, p = id % NP2;
        int l, m, n; dec_p2(p, &l, &m, &n);
        float v = (float)wigd(l, m, n, PI_D*(2*k+1)/32.0);
        g_dL2[id] = v;
        if (m >= 0)
            g_dL2h[k*NH2 + c_choff[l] + m*(2*l+1) + (n+l)] =
                (float)(2*l+1) * (m > 0 ? 2.f : 1.f) * v;
        return;
    }
    id -= 16*NP2;
    if (id < 3*NP2F) {                                  // g_dG
        int gi = id / NP2F, p = id % NP2F;
        int l, m, n; dec_p2(p, &l, &m, &n);
        g_dG[id] = (float)wigd(l, m, n, (gi+1)*PI_D/24.0);
    }
}

__global__ void k_weights() {
    int id = threadIdx.x;
    int b, j; float* dst;
    if (id < 128)      { b = 64; j = id;       dst = &g_Win[j]; }
    else if (id < 160) { b = 16; j = id - 128; dst = &g_Wl1[j]; }
    else if (id < 176) { b = 8;  j = id - 160; dst = &g_Wl2[j]; }
    else return;
    double s = 0.0;
    for (int l2 = 0; l2 < b; l2++)
        s += sin((2.0*j+1)*(2.0*l2+1)*PI_D/(4.0*b)) / (2.0*l2+1);
    *dst = (float)((2.0/b)*sin(PI_D*(2*j+1)/(4.0*b))*s);
}

__global__ void k_prep() {
    int id = blockIdx.x*256 + threadIdx.x;              // 32*680 = 21760
    if (id < 32*NP2) {
        int k = id / NP2, p = id % NP2;
        g_cf1[id] = (float)(2.0*PI_D) * g_Wl1[k] * g_dL1[k*NP2F + p];
    }
    if (id < NP2) {
        int l, m, n; dec_p2(id, &l, &m, &n);
        g_mnidx[id] = (m+7)*15 + (n+7);
    }
}

__global__ void k_psi3gen() {
    int id = blockIdx.x*256 + threadIdx.x;              // 680*192
    if (id >= NP2*192) return;
    int p2 = id / 192, g = id % 192;
    int l, m, n; dec_p2(p2, &l, &m, &n);
    int ia = (g>>3)&7, ic = g&7, ib = g>>6;
    float d = g_dG[ib*NP2F + p2];
    int ph = ((m-n)*ia + n*ic + 160) & 7;               // conj: e^{+i(m a + n g)}
    float s, c; sincosf((float)ph * (float)(PI_D/4.0), &s, &c);
    g_psi3[id] = make_float2(d*c, d*s);
}

// ------------------------- S2 stage ----------------------------------------
__global__ void k_dft1(const float* __restrict__ x) {
    int bid = blockIdx.x;                               // b*128 + k
    __shared__ float xs[128], tcr[128], tci[128];
    int tid = threadIdx.x;                              // 64
    xs[tid]      = x[bid*128 + tid];
    xs[tid+64]   = x[bid*128 + tid + 64];
    float s, c;
    sincosf((float)tid      * (float)(-2.0*PI_D/128.0), &s, &c); tcr[tid]=c;    tci[tid]=s;
    sincosf((float)(tid+64) * (float)(-2.0*PI_D/128.0), &s, &c); tcr[tid+64]=c; tci[tid+64]=s;
    __syncthreads();
    if (tid < 31) {
        int m = tid - 15;
        float ar = 0.f, ai = 0.f;
        for (int a = 0; a < 128; a++) {
            int j = ((m+128)*a) & 127;
            ar += xs[a]*tcr[j];
            ai += xs[a]*tci[j];
        }
        g_xf1[tid*2048 + bid] = make_float2(ar, ai);
    }
}

__global__ void k_fx() {
    int id = blockIdx.x*256 + threadIdx.x;              // 4096
    if (id >= 4096) return;
    int b = id & 15, p1 = id >> 4;
    int l = 0; while ((l+1)*(l+1) <= p1) l++;
    int m = p1 - l*l - l;
    float sr = 0.f, si = 0.f;
    for (int kk = 0; kk < 128; kk++) {
        float w = g_Win[kk]*g_dcol[p1*128 + kk];
        float2 v = g_xf1[(m+15)*2048 + b*128 + kk];
        sr += w*v.x; si += w*v.y;
    }
    float sc = (float)(2.0*PI_D/128.0);
    g_Fx[b*256 + p1] = make_float2(sr*sc, si*sc);
}

__global__ void k_fyc(const float* __restrict__ w1) {
    int id = blockIdx.x*256 + threadIdx.x;              // 16384
    if (id >= 16384) return;
    int p1 = id >> 6, o = id & 63;
    int l = 0; while ((l+1)*(l+1) <= p1) l++;
    int m = p1 - l*l - l;
    int dbase = c_off2[l] + (m+l)*(2*l+1) + l;          // column n=0
    float sr = 0.f, si = 0.f;
    for (int g = 0; g < 24; g++) {
        int ib = g >> 3, ia = g & 7;
        float d = g_dG[ib*NP2F + dbase];
        int ph = (m*ia + 120) & 7;                      // conj: e^{+i m a}
        float sn, cs; sincosf((float)ph*(float)(PI_D/4.0), &sn, &cs);
        float wv = w1[o*24 + g];
        sr += wv*d*cs;
        si += wv*d*sn;
    }
    g_FyC[o*256 + p1] = make_float2(sr, si);
}

// ------------------------- fused middle stage ------------------------------
__global__ void __launch_bounds__(256) k_mid() {
    int bid = blockIdx.x;                               // 32768
    int k = bid & 31, f = (bid>>5)&63, b = bid>>11;
    __shared__ float  ds[NH1];
    __shared__ float2 fxs[256], fycs[256];
    __shared__ float2 Ss[16*31];                        // [m][ni]  (m>0 doubled)
    __shared__ float2 Rs[32*31];                        // [a][ni]
    __shared__ float  ys[1024];                         // [a][c]
    __shared__ float2 Us[8*32];
    __shared__ float2 tws[32];                          // e^{+2pi i j/32}
    int tid = threadIdx.x;

    {
        const float4* src = (const float4*)(g_dL1h + k*NH1);
        float4* dst = (float4*)ds;
        for (int i = tid; i < NH1/4; i += 256) dst[i] = src[i];
    }
    fxs[tid]  = g_Fx[b*256 + tid];
    fycs[tid] = g_FyC[f*256 + tid];
    if (tid < 32) {
        float s, c; sincosf((float)tid*(float)(2.0*PI_D/32.0), &s, &c);
        tws[tid] = make_float2(c, s);
    }
    __syncthreads();

    // S[m,ni] = sum_l wfold * Fx[l,m] FyC[l,n],  m=0..15, n=ni-15
    for (int idx = tid; idx < 496; idx += 256) {
        int mi = idx / 31, ni = idx - mi*31;
        int n = ni - 15;
        int an = n < 0 ? -n : n;
        int lmin = mi > an ? mi : an;
        int ch = (lmin*(lmin+1)*(4*lmin-1))/6;
        int q  = lmin*lmin + lmin;
        float sr = 0.f, si = 0.f;
        for (int l = lmin; l < 16; l++) {
            int D = 2*l+1;
            float w   = ds[ch + mi*D + n + l];
            float2 av = fxs[q + mi];
            float2 bv = fycs[q + n];
            sr += w*(av.x*bv.x - av.y*bv.y);
            si += w*(av.x*bv.y + av.y*bv.x);
            ch += (l+1)*D;
            q  += 2*l + 2;
        }
        Ss[idx] = make_float2(sr, si);
    }
    __syncthreads();

    // R[a,ni] = sum_{m=0..15} Ss[m,ni] e^{+i m a 2pi/32}  (shared recurrence)
    {
        int a = tid & 31, nbase = (tid >> 5) * 4;
        float2 step = tws[a];
        float2 w = make_float2(1.f, 0.f);
        float2 acc0 = {0,0}, acc1 = {0,0}, acc2 = {0,0}, acc3 = {0,0};
        bool full = (nbase + 3 < 31);
        for (int m = 0; m < 16; m++) {
            float2 s0 = Ss[m*31 + nbase];
            float2 s1 = Ss[m*31 + nbase + 1];
            float2 s2 = Ss[m*31 + nbase + 2];
            acc0.x += s0.x*w.x - s0.y*w.y;  acc0.y += s0.x*w.y + s0.y*w.x;
            acc1.x += s1.x*w.x - s1.y*w.y;  acc1.y += s1.x*w.y + s1.y*w.x;
            acc2.x += s2.x*w.x - s2.y*w.y;  acc2.y += s2.x*w.y + s2.y*w.x;
            if (full) {
                float2 s3 = Ss[m*31 + nbase + 3];
                acc3.x += s3.x*w.x - s3.y*w.y;  acc3.y += s3.x*w.y + s3.y*w.x;
            }
            float nr = w.x*step.x - w.y*step.y;
            w.y = w.x*step.y + w.y*step.x;
            w.x = nr;
        }
        Rs[a*31 + nbase]     = acc0;
        Rs[a*31 + nbase + 1] = acc1;
        Rs[a*31 + nbase + 2] = acc2;
        if (full) Rs[a*31 + nbase + 3] = acc3;
    }
    __syncthreads();

    // y[a,c] = relu( Re sum_{ni} Rs[a,ni] e^{+i (ni-15) c 2pi/32} )
    // hoisted single recurrence (w depends only on c) + ni/ni+16 pairing
    // (e^{i16c} = (-1)^c) + exact ni=15 term (w == 1).
    {
        int c = tid & 31, a0 = tid >> 5;
        float2 step = tws[c];
        float2 w = tws[(17*c) & 31];                    // e^{-i 15 c}
        float sgn = (c & 1) ? -1.f : 1.f;
        float v0 = 0.f, v1 = 0.f, v2 = 0.f, v3 = 0.f;
        for (int ni = 0; ni < 15; ni++) {
            float2 rA0 = Rs[(a0     )*31 + ni], rB0 = Rs[(a0     )*31 + ni + 16];
            float2 rA1 = Rs[(a0 +  8)*31 + ni], rB1 = Rs[(a0 +  8)*31 + ni + 16];
            float2 rA2 = Rs[(a0 + 16)*31 + ni], rB2 = Rs[(a0 + 16)*31 + ni + 16];
            float2 rA3 = Rs[(a0 + 24)*31 + ni], rB3 = Rs[(a0 + 24)*31 + ni + 16];
            float er, ei;
            er = rA0.x + sgn*rB0.x; ei = rA0.y + sgn*rB0.y; v0 += er*w.x - ei*w.y;
            er = rA1.x + sgn*rB1.x; ei = rA1.y + sgn*rB1.y; v1 += er*w.x - ei*w.y;
            er = rA2.x + sgn*rB2.x; ei = rA2.y + sgn*rB2.y; v2 += er*w.x - ei*w.y;
            er = rA3.x + sgn*rB3.x; ei = rA3.y + sgn*rB3.y; v3 += er*w.x - ei*w.y;
            float nr = w.x*step.x - w.y*step.y;
            w.y = w.x*step.y + w.y*step.x;
            w.x = nr;
        }
        v0 += Rs[(a0     )*31 + 15].x;
        v1 += Rs[(a0 +  8)*31 + 15].x;
        v2 += Rs[(a0 + 16)*31 + 15].x;
        v3 += Rs[(a0 + 24)*31 + 15].x;
        ys[(a0     )*32 + c] = fmaxf(v0, 0.f);
        ys[(a0 +  8)*32 + c] = fmaxf(v1, 0.f);
        ys[(a0 + 16)*32 + c] = fmaxf(v2, 0.f);
        ys[(a0 + 24)*32 + c] = fmaxf(v3, 0.f);
    }
    __syncthreads();

    // U[m,c] = sum_a y[a,c] e^{-i m a 2pi/32}, m=0..7
    // a/a+16 pairing: e^{-i m 16 th} = (-1)^m.
    {
        int m = tid >> 5, c = tid & 31;
        float2 st = tws[m]; st.y = -st.y;               // e^{-i m}
        float2 w = make_float2(1.f, 0.f);
        float sgn = (m & 1) ? -1.f : 1.f;
        float ur = 0.f, ui = 0.f;
        for (int a = 0; a < 16; a++) {
            float ye = ys[a*32 + c] + sgn*ys[(a+16)*32 + c];
            ur += ye*w.x; ui += ye*w.y;
            float nr = w.x*st.x - w.y*st.y;
            w.y = w.x*st.y + w.y*st.x;
            w.x = nr;
        }
        Us[tid] = make_float2(ur, ui);
    }
    __syncthreads();

    // V[m,n] = (1/1024) sum_c U[m,c] e^{-i n c 2pi/32}; mirror via conj sym
    const float s1 = 1.0f/1024.0f;
    size_t base = ((size_t)k*1024u + (size_t)(b*64+f))*225u;
    for (int idx = tid; idx < 120; idx += 256) {
        int m = idx/15, ni = idx%15, n = ni-7;
        float vr = 0.f, vi = 0.f;
        for (int c = 0; c < 32; c++) {
            int j = ((n+32)*c) & 31;
            float2 u = Us[m*32 + c];
            float2 t = tws[j];
            vr +=  u.x*t.x + u.y*t.y;
            vi += -u.x*t.y + u.y*t.x;
        }
        vr *= s1; vi *= s1;
        g_xf2[base + (m+7)*15 + ni] = make_float2(vr, vi);
        if (m > 0)
            g_xf2[base + (7-m)*15 + (14-ni)] = make_float2(vr, -vi);
    }
}

// ------------------------- Fx2 contraction over k --------------------------
__global__ void __launch_bounds__(256) k_fx2() {
    int bf0 = blockIdx.x * 4;                           // 256 blocks
    __shared__ float2 accs[NP2*4];
    __shared__ float2 tile[4*225];
    __shared__ float  coefs[NP2];
    __shared__ int    mns[NP2];
    int tid = threadIdx.x;
    for (int i = tid; i < NP2*4; i += 256) accs[i] = make_float2(0.f, 0.f);
    for (int i = tid; i < NP2;   i += 256) mns[i]  = g_mnidx[i];
    __syncthreads();
    for (int kk = 0; kk < 32; kk++) {
        for (int i = tid; i < 900; i += 256) {
            int j = i/225, mn = i%225;
            tile[j*225 + mn] = g_xf2[((size_t)kk*1024u + bf0 + j)*225u + mn];
        }
        for (int i = tid; i < NP2; i += 256) coefs[i] = g_cf1[kk*NP2 + i];
        __syncthreads();
        for (int i = tid; i < NP2*4; i += 256) {
            int p2 = i >> 2, j = i & 3;
            float  w = coefs[p2];
            float2 v = tile[j*225 + mns[p2]];
            accs[i].x += w*v.x;
            accs[i].y += w*v.y;
        }
        __syncthreads();
    }
    for (int i = tid; i < NP2*4; i += 256) {
        int p2 = i >> 2, j = i & 3;
        g_Fx2[(size_t)p2*1024u + bf0 + j] = accs[i];
    }
}

// ------------------------- Fy2 (conj) build --------------------------------
__global__ void __launch_bounds__(256) k_fy2(const float* __restrict__ w2) {
    __shared__ float  w2s[1024*9];
    __shared__ float2 psis[64];
    int p20 = blockIdx.x * 8;                           // 85 tiles
    int io0 = blockIdx.y * 1024;                        // 8 tiles
    int tid = threadIdx.x;
    float aR[8][4], aI[8][4];
    #pragma unroll
    for (int p = 0; p < 8; p++)
        #pragma unroll
        for (int q = 0; q < 4; q++) { aR[p][q] = 0.f; aI[p][q] = 0.f; }
    for (int gc = 0; gc < 192; gc += 8) {
        for (int i = tid; i < 8192; i += 256) {
            int iol = i >> 3, g = i & 7;
            w2s[iol*9 + g] = w2[(size_t)(io0+iol)*192 + gc + g];
        }
        if (tid < 64) {
            int pj = tid >> 3, g = tid & 7;
            psis[tid] = g_psi3[(p20+pj)*192 + gc + g];
        }
        __syncthreads();
        #pragma unroll
        for (int g = 0; g < 8; g++) {
            float pr[8], pim[8];
            #pragma unroll
            for (int pj = 0; pj < 8; pj++) {
                float2 v = psis[pj*8 + g];
                pr[pj] = v.x; pim[pj] = v.y;
            }
            #pragma unroll
            for (int ioj = 0; ioj < 4; ioj++) {
                float w = w2s[(ioj*256 + tid)*9 + g];
                #pragma unroll
                for (int pj = 0; pj < 8; pj++) {
                    aR[pj][ioj] += w*pr[pj];
                    aI[pj][ioj] += w*pim[pj];
                }
            }
        }
        __syncthreads();
    }
    #pragma unroll
    for (int pj = 0; pj < 8; pj++)
        #pragma unroll
        for (int ioj = 0; ioj < 4; ioj++)
            g_Fy2[(size_t)(p20+pj)*8192u + io0 + ioj*256 + tid] =
                make_float2(aR[pj][ioj], aI[pj][ioj]);
}

// ------------------------- Fz2 batched complex GEMM (split-k) --------------
__global__ void __launch_bounds__(256) k_fz2() {
    int bid2 = blockIdx.x;                              // 1360 = 2 x 680
    int half = bid2 >= 680;
    int bid = bid2 - half*680;
    int l = 0; while (c_off2[l+1] <= bid) l++;
    int r = bid - c_off2[l], D = 2*l+1;
    int mi = r / D, ni = r % D;
    int kmid = (D+1) >> 1;
    int kw0 = half ? kmid : 0;
    int kw1 = half ? D : kmid;
    __shared__ float2 As[256];                          // [b16][ii16]
    __shared__ float2 Bs[2048];                         // [ii16][o128]
    int tid = threadIdx.x;
    int o = tid & 127, bh = tid >> 7;
    float aR[8], aI[8];
    #pragma unroll
    for (int j = 0; j < 8; j++) { aR[j] = 0.f; aI[j] = 0.f; }
    for (int kw = kw0; kw < kw1; kw++) {
        size_t p2A = (size_t)(c_off2[l] + mi*D + kw);
        size_t p2B = (size_t)(c_off2[l] + ni*D + kw);
        for (int ic = 0; ic < 4; ic++) {
            { int bb = tid >> 4, ii = tid & 15;
              As[tid] = g_Fx2[p2A*1024u + bb*64 + ic*16 + ii]; }
            for (int rr = tid; rr < 2048; rr += 256) {
                int ii = rr >> 7, oo = rr & 127;
                Bs[rr] = g_Fy2[p2B*8192u + (ic*16+ii)*128 + oo];
            }
            __syncthreads();
            #pragma unroll 4
            for (int ii = 0; ii < 16; ii++) {
                float2 bv = Bs[ii*128 + o];
                #pragma unroll
                for (int bj = 0; bj < 8; bj++) {
                    float2 av = As[(bh*8+bj)*16 + ii];
                    aR[bj] += av.x*bv.x - av.y*bv.y;
                    aI[bj] += av.x*bv.y + av.y*bv.x;
                }
            }
            __syncthreads();
        }
    }
    float2* dst = half ? g_Fz2b : g_Fz2;
    #pragma unroll
    for (int bj = 0; bj < 8; bj++) {
        int bb = bh*8 + bj;
        dst[(size_t)(bb*128 + o)*NP2 + bid] = make_float2(aR[bj], aI[bj]);
    }
}

// ------------------------- final fused iSO3 + relu + mean ------------------
__global__ void __launch_bounds__(256) k_final() {
    int bo = blockIdx.x;                                // 2048
    __shared__ float2 Fzs[NP2];
    __shared__ float  d2s[NH2];
    __shared__ float2 Ss[8*15];
    __shared__ float2 Rs[16*15];
    __shared__ float2 tws[16];
    __shared__ float  red[256];
    int tid = threadIdx.x;
    for (int i = tid; i < NP2; i += 256) {
        float2 a = g_Fz2[(size_t)bo*NP2 + i];
        float2 b = g_Fz2b[(size_t)bo*NP2 + i];
        Fzs[i] = make_float2(a.x + b.x, a.y + b.y);
    }
    if (tid < 16) {
        float s, c; sincosf((float)tid*(float)(2.0*PI_D/16.0), &s, &c);
        tws[tid] = make_float2(c, s);                   // e^{+2pi i j/16}
    }
    float accum = 0.f;
    for (int k2 = 0; k2 < 16; k2++) {
        for (int i = tid; i < NH2; i += 256) d2s[i] = g_dL2h[k2*NH2 + i];
        __syncthreads();
        if (tid < 120) {
            int mi = tid/15, ni = tid%15, n = ni-7;
            int an = n < 0 ? -n : n;
            int lmin = mi > an ? mi : an;
            int ch = (lmin*(lmin+1)*(4*lmin-1))/6;
            int co = (4*lmin*lmin*lmin - lmin)/3;
            float sr = 0.f, si = 0.f;
            for (int l = lmin; l < 8; l++) {
                int D = 2*l+1;
                float w = d2s[ch + mi*D + n + l];
                float2 fz = Fzs[co + (mi+l)*D + (n+l)];
                sr += w*fz.x; si += w*fz.y;
                ch += (l+1)*D;
                co += D*D;
            }
            Ss[mi*15 + ni] = make_float2(sr, si);
        }
        __syncthreads();
        if (tid < 240) {
            int a = tid & 15, ni = tid >> 4;
            float2 step = tws[a];
            float2 w = make_float2(1.f, 0.f);
            float2 acc = {0,0};
            for (int m = 0; m < 8; m++) {
                float2 s = Ss[m*15 + ni];
                acc.x += s.x*w.x - s.y*w.y;
                acc.y += s.x*w.y + s.y*w.x;
                float nr = w.x*step.x - w.y*step.y;
                w.y = w.x*step.y + w.y*step.x;
                w.x = nr;
            }
            Rs[a*15 + ni] = acc;
        }
        __syncthreads();
        {
            int a = tid >> 4, c = tid & 15;
            float2 step = tws[c];
            float2 w = tws[(9*c) & 15];                 // e^{-i 7 c}
            float v = 0.f;
            for (int ni = 0; ni < 15; ni++) {
                float2 r = Rs[a*15 + ni];
                v += r.x*w.x - r.y*w.y;
                float nr = w.x*step.x - w.y*step.y;
                w.y = w.x*step.y + w.y*step.x;
                w.x = nr;
            }
            accum += fmaxf(v, 0.f) * g_Wl2[k2];
        }
        __syncthreads();
    }
    red[tid] = accum * (1.0f/256.0f);
    __syncthreads();
    for (int s = 128; s > 0; s >>= 1) {
        if (tid < s) red[tid] += red[tid + s];
        __syncthreads();
    }
    if (tid == 0) g_feat[bo] = red[0];
}

// ------------------------- linear head -------------------------------------
__global__ void k_head(const float* __restrict__ lw,
                       const float* __restrict__ lb,
                       float* __restrict__ out) {
    int t = threadIdx.x;
    if (t < 160) {
        int b = t / 10, j = t % 10;
        float s = lb[j];
        for (int o = 0; o < 128; o++)
            s += g_feat[b*128 + o] * lw[j*128 + o];
        out[t] = s;
    }
}

// ------------------------- launcher ----------------------------------------
extern "C" void kernel_launch(void* const* d_in, const int* in_sizes, int n_in,
                              void* d_out, int out_size) {
    const float* x  = (const float*)d_in[0];
    const float* w1 = (const float*)d_in[1];
    const float* w2 = (const float*)d_in[2];
    const float* lw = (const float*)d_in[3];
    const float* lb = (const float*)d_in[4];
    float* out = (float*)d_out;

    // order chosen so ncu (-s 5 -c 1) captures k_mid (6th launch)
    k_tables<<<917, 256>>>();                           // 1
    k_weights<<<1, 192>>>();                            // 2
    k_dft1<<<2048, 64>>>(x);                            // 3
    k_fx<<<16, 256>>>();                                // 4
    k_fyc<<<64, 256>>>(w1);                             // 5
    k_mid<<<32768, 256>>>();                            // 6  <- profiled
    k_prep<<<85, 256>>>();
    k_psi3gen<<<510, 256>>>();
    k_fx2<<<256, 256>>>();
    k_fy2<<<dim3(85, 8), 256>>>(w2);
    k_fz2<<<1360, 256>>>();
    k_final<<<2048, 256>>>();
    k_head<<<1, 192>>>(lw, lb, out);
}

// round 16
// speedup vs baseline: 1.6507x; 1.1407x over previous
#include <cuda_runtime.h>
#include <cuda_bf16.h>
#include <math.h>

// ============================================================================
// S2ConvNet forward on GB300.
//   x(16,1,128,128) f32 -> out(16,10) f32
// R15: k_fz2 computes only the m>=0 half-tiles actually consumed by k_final
// (-46% flops, exact); k_fx/k_fyc merged (fixes 23us latency-bound k_fx);
// k_weights folded into k_tables; k_mid is now launch #4 (= ncu capture slot).
// ============================================================================

#define PI_D 3.14159265358979323846

#define NP1   256      // sum_{l<16}(2l+1)
#define NP2F  5456     // sum_{l<16}(2l+1)^2
#define NP2   680      // sum_{l<8}(2l+1)^2
#define NH1   2856     // sum_{l<16}(l+1)(2l+1)
#define NH2   372      // sum_{l<8}(l+1)(2l+1)
#define BF    1024     // BATCH*F1
#define BO    2048     // BATCH*F2

__constant__ int c_off2[17] = {0,1,10,35,84,165,286,455,680,969,1330,1771,
                               2300,2925,3654,4495,5456};
__constant__ int c_choff[17] = {0,1,7,22,50,95,161,252,372,525,715,946,
                                1222,1547,1925,2360,2856};

// ------------------------- device global scratch ---------------------------
__device__ float  g_Win[128];
__device__ float  g_Wl1[32];
__device__ float  g_Wl2[16];
__device__ float  g_dcol[256*128];          // [p1][k]  d^l_{m0}(beta_in_k)
__device__ float  g_dL1[32*NP2F];           // [k][p2f] full d, L1 betas
__device__ float  g_dL2[16*NP2];            // [k][p2]  full d, L2 betas
__device__ float  g_dG[3*NP2F];             // [gbeta][p2f] full d, grid betas
__device__ __align__(16) float g_dL1h[32*NH1];  // folded: (2l+1)*(m>0?2:1)*d
__device__ __align__(16) float g_dL2h[16*NH2];
__device__ float  g_cf1[32*NP2];            // 2pi*Wl1[k]*dL1 (l<8)
__device__ int    g_mnidx[NP2];             // p2 -> (m+7)*15+(n+7)
__device__ float2 g_psi3[NP2*192];          // conj(psi_SO3)
__device__ float2 g_xf1[31*2048];           // [m+15][b*128+k]
__device__ float2 g_Fx[16*256];             // [b][p1]
__device__ float2 g_FyC[64*256];            // [o][p1]  (conj applied)
__device__ float2 g_xf2[32u*1024u*225u];    // [k][bf][mn]  (59 MB)
__device__ float2 g_Fx2[NP2*BF];            // [p2][bf]
__device__ float2 g_Fy2[NP2*8192];          // [p2][i*128+o] (conj applied)
__device__ float2 g_Fz2h[BO*NH2];           // [b*128+o][jh]  (kw half 0)
__device__ float2 g_Fz2hb[BO*NH2];          // [b*128+o][jh]  (kw half 1)
__device__ float  g_feat[BO];

// ------------------------- Wigner small-d (fp64) ---------------------------
__device__ double wigd(int l, int m, int n, double beta) {
    double fact[32];
    fact[0] = 1.0;
    for (int i = 1; i < 32; i++) fact[i] = fact[i-1] * (double)i;
    double ch = cos(0.5*beta), sh = sin(0.5*beta);
    int smin = n - m; if (smin < 0) smin = 0;
    int smax = l + n; if (l - m < smax) smax = l - m;
    double pref = sqrt(fact[l+m]*fact[l-m]*fact[l+n]*fact[l-n]);
    double sum = 0.0;
    for (int s = smin; s <= smax; s++) {
        int ae = 2*l + n - m - 2*s;
        int be = m - n + 2*s;
        double pc = 1.0; for (int i = 0; i < ae; i++) pc *= ch;
        double ps = 1.0; for (int i = 0; i < be; i++) ps *= sh;
        double t = pref/(fact[l+n-s]*fact[s]*fact[m-n+s]*fact[l-m-s])*pc*ps;
        sum += ((m-n+s)&1) ? -t : t;
    }
    return sum;
}

__device__ __forceinline__ void dec_p2(int p, int* lo, int* mo, int* no) {
    int l = 0;
    while (c_off2[l+1] <= p) l++;
    int r = p - c_off2[l], D = 2*l+1;
    *lo = l; *mo = r/D - l; *no = r%D - l;
}

// ------------------------- table generation (incl. DH weights) -------------
__global__ void k_tables() {
    int id = blockIdx.x*blockDim.x + threadIdx.x;
    if (id < 32768) {                                   // g_dcol
        int p1 = id >> 7, k = id & 127;
        int l = 0; while ((l+1)*(l+1) <= p1) l++;
        int m = p1 - l*l - l;
        g_dcol[id] = (float)wigd(l, m, 0, PI_D*(2*k+1)/256.0);
        return;
    }
    id -= 32768;
    if (id < 32*NP2F) {                                 // g_dL1 (+ folded half)
        int k = id / NP2F, p = id % NP2F;
        int l, m, n; dec_p2(p, &l, &m, &n);
        float v = (float)wigd(l, m, n, PI_D*(2*k+1)/64.0);
        g_dL1[id] = v;
        if (m >= 0)
            g_dL1h[k*NH1 + c_choff[l] + m*(2*l+1) + (n+l)] =
                (float)(2*l+1) * (m > 0 ? 2.f : 1.f) * v;
        return;
    }
    id -= 32*NP2F;
    if (id < 16*NP2) {                                  // g_dL2 (+ folded half)
        int k = id / NP2, p = id % NP2;
        int l, m, n; dec_p2(p, &l, &m, &n);
        float v = (float)wigd(l, m, n, PI_D*(2*k+1)/32.0);
        g_dL2[id] = v;
        if (m >= 0)
            g_dL2h[k*NH2 + c_choff[l] + m*(2*l+1) + (n+l)] =
                (float)(2*l+1) * (m > 0 ? 2.f : 1.f) * v;
        return;
    }
    id -= 16*NP2;
    if (id < 3*NP2F) {                                  // g_dG
        int gi = id / NP2F, p = id % NP2F;
        int l, m, n; dec_p2(p, &l, &m, &n);
        g_dG[id] = (float)wigd(l, m, n, (gi+1)*PI_D/24.0);
        return;
    }
    id -= 3*NP2F;
    if (id < 176) {                                     // DH quadrature weights
        int b, j; float* dst;
        if (id < 128)      { b = 64; j = id;       dst = &g_Win[j]; }
        else if (id < 160) { b = 16; j = id - 128; dst = &g_Wl1[j]; }
        else               { b = 8;  j = id - 160; dst = &g_Wl2[j]; }
        double s = 0.0;
        for (int l2 = 0; l2 < b; l2++)
            s += sin((2.0*j+1)*(2.0*l2+1)*PI_D/(4.0*b)) / (2.0*l2+1);
        *dst = (float)((2.0/b)*sin(PI_D*(2*j+1)/(4.0*b))*s);
    }
}

__global__ void k_prep() {
    int id = blockIdx.x*256 + threadIdx.x;              // 32*680 = 21760
    if (id < 32*NP2) {
        int k = id / NP2, p = id % NP2;
        g_cf1[id] = (float)(2.0*PI_D) * g_Wl1[k] * g_dL1[k*NP2F + p];
    }
    if (id < NP2) {
        int l, m, n; dec_p2(id, &l, &m, &n);
        g_mnidx[id] = (m+7)*15 + (n+7);
    }
}

__global__ void k_psi3gen() {
    int id = blockIdx.x*256 + threadIdx.x;              // 680*192
    if (id >= NP2*192) return;
    int p2 = id / 192, g = id % 192;
    int l, m, n; dec_p2(p2, &l, &m, &n);
    int ia = (g>>3)&7, ic = g&7, ib = g>>6;
    float d = g_dG[ib*NP2F + p2];
    int ph = ((m-n)*ia + n*ic + 160) & 7;               // conj: e^{+i(m a + n g)}
    float s, c; sincosf((float)ph * (float)(PI_D/4.0), &s, &c);
    g_psi3[id] = make_float2(d*c, d*s);
}

// ------------------------- S2 stage ----------------------------------------
__global__ void k_dft1(const float* __restrict__ x) {
    int bid = blockIdx.x;                               // b*128 + k
    __shared__ float xs[128], tcr[128], tci[128];
    int tid = threadIdx.x;                              // 64
    xs[tid]      = x[bid*128 + tid];
    xs[tid+64]   = x[bid*128 + tid + 64];
    float s, c;
    sincosf((float)tid      * (float)(-2.0*PI_D/128.0), &s, &c); tcr[tid]=c;    tci[tid]=s;
    sincosf((float)(tid+64) * (float)(-2.0*PI_D/128.0), &s, &c); tcr[tid+64]=c; tci[tid+64]=s;
    __syncthreads();
    if (tid < 31) {
        int m = tid - 15;
        float ar = 0.f, ai = 0.f;
        for (int a = 0; a < 128; a++) {
            int j = ((m+128)*a) & 127;
            ar += xs[a]*tcr[j];
            ai += xs[a]*tci[j];
        }
        g_xf1[tid*2048 + bid] = make_float2(ar, ai);
    }
}

// merged Fx + FyC build (80 blocks: hides k_fx's 128-deep load latency)
__global__ void k_fxfyc(const float* __restrict__ w1) {
    int id = blockIdx.x*256 + threadIdx.x;              // 20480
    if (id < 4096) {                                    // Fx
        int b = id & 15, p1 = id >> 4;
        int l = 0; while ((l+1)*(l+1) <= p1) l++;
        int m = p1 - l*l - l;
        float sr = 0.f, si = 0.f;
        #pragma unroll 4
        for (int kk = 0; kk < 128; kk++) {
            float w = g_Win[kk]*g_dcol[p1*128 + kk];
            float2 v = g_xf1[(m+15)*2048 + b*128 + kk];
            sr += w*v.x; si += w*v.y;
        }
        float sc = (float)(2.0*PI_D/128.0);
        g_Fx[b*256 + p1] = make_float2(sr*sc, si*sc);
        return;
    }
    id -= 4096;
    if (id < 16384) {                                   // FyC
        int p1 = id >> 6, o = id & 63;
        int l = 0; while ((l+1)*(l+1) <= p1) l++;
        int m = p1 - l*l - l;
        int dbase = c_off2[l] + (m+l)*(2*l+1) + l;      // column n=0
        float sr = 0.f, si = 0.f;
        for (int g = 0; g < 24; g++) {
            int ib = g >> 3, ia = g & 7;
            float d = g_dG[ib*NP2F + dbase];
            int ph = (m*ia + 120) & 7;                  // conj: e^{+i m a}
            float sn, cs; sincosf((float)ph*(float)(PI_D/4.0), &sn, &cs);
            float wv = w1[o*24 + g];
            sr += wv*d*cs;
            si += wv*d*sn;
        }
        g_FyC[o*256 + p1] = make_float2(sr, si);
    }
}

// ------------------------- fused middle stage ------------------------------
__global__ void __launch_bounds__(256) k_mid() {
    int bid = blockIdx.x;                               // 32768
    int k = bid & 31, f = (bid>>5)&63, b = bid>>11;
    __shared__ float  ds[NH1];
    __shared__ float2 fxs[256], fycs[256];
    __shared__ float2 Ss[16*31];                        // [m][ni]  (m>0 doubled)
    __shared__ float2 Rs[32*31];                        // [a][ni]
    __shared__ float  ys[1024];                         // [a][c]
    __shared__ float2 Us[8*32];
    __shared__ float2 tws[32];                          // e^{+2pi i j/32}
    int tid = threadIdx.x;

    {
        const float4* src = (const float4*)(g_dL1h + k*NH1);
        float4* dst = (float4*)ds;
        for (int i = tid; i < NH1/4; i += 256) dst[i] = src[i];
    }
    fxs[tid]  = g_Fx[b*256 + tid];
    fycs[tid] = g_FyC[f*256 + tid];
    if (tid < 32) {
        float s, c; sincosf((float)tid*(float)(2.0*PI_D/32.0), &s, &c);
        tws[tid] = make_float2(c, s);
    }
    __syncthreads();

    // S[m,ni] = sum_l wfold * Fx[l,m] FyC[l,n],  m=0..15, n=ni-15
    for (int idx = tid; idx < 496; idx += 256) {
        int mi = idx / 31, ni = idx - mi*31;
        int n = ni - 15;
        int an = n < 0 ? -n : n;
        int lmin = mi > an ? mi : an;
        int ch = (lmin*(lmin+1)*(4*lmin-1))/6;
        int q  = lmin*lmin + lmin;
        float sr = 0.f, si = 0.f;
        for (int l = lmin; l < 16; l++) {
            int D = 2*l+1;
            float w   = ds[ch + mi*D + n + l];
            float2 av = fxs[q + mi];
            float2 bv = fycs[q + n];
            sr += w*(av.x*bv.x - av.y*bv.y);
            si += w*(av.x*bv.y + av.y*bv.x);
            ch += (l+1)*D;
            q  += 2*l + 2;
        }
        Ss[idx] = make_float2(sr, si);
    }
    __syncthreads();

    // R[a,ni] = sum_{m=0..15} Ss[m,ni] e^{+i m a 2pi/32}
    {
        int a = tid & 31, nbase = (tid >> 5) * 4;
        float2 step = tws[a];
        float2 w = make_float2(1.f, 0.f);
        float2 acc0 = {0,0}, acc1 = {0,0}, acc2 = {0,0}, acc3 = {0,0};
        bool full = (nbase + 3 < 31);
        for (int m = 0; m < 16; m++) {
            float2 s0 = Ss[m*31 + nbase];
            float2 s1 = Ss[m*31 + nbase + 1];
            float2 s2 = Ss[m*31 + nbase + 2];
            acc0.x += s0.x*w.x - s0.y*w.y;  acc0.y += s0.x*w.y + s0.y*w.x;
            acc1.x += s1.x*w.x - s1.y*w.y;  acc1.y += s1.x*w.y + s1.y*w.x;
            acc2.x += s2.x*w.x - s2.y*w.y;  acc2.y += s2.x*w.y + s2.y*w.x;
            if (full) {
                float2 s3 = Ss[m*31 + nbase + 3];
                acc3.x += s3.x*w.x - s3.y*w.y;  acc3.y += s3.x*w.y + s3.y*w.x;
            }
            float nr = w.x*step.x - w.y*step.y;
            w.y = w.x*step.y + w.y*step.x;
            w.x = nr;
        }
        Rs[a*31 + nbase]     = acc0;
        Rs[a*31 + nbase + 1] = acc1;
        Rs[a*31 + nbase + 2] = acc2;
        if (full) Rs[a*31 + nbase + 3] = acc3;
    }
    __syncthreads();

    // y[a,c] = relu( Re sum_{ni} Rs[a,ni] e^{+i (ni-15) c 2pi/32} )
    {
        int c = tid & 31, a0 = tid >> 5;
        float2 step = tws[c];
        float2 w = tws[(17*c) & 31];                    // e^{-i 15 c}
        float sgn = (c & 1) ? -1.f : 1.f;
        float v0 = 0.f, v1 = 0.f, v2 = 0.f, v3 = 0.f;
        for (int ni = 0; ni < 15; ni++) {
            float2 rA0 = Rs[(a0     )*31 + ni], rB0 = Rs[(a0     )*31 + ni + 16];
            float2 rA1 = Rs[(a0 +  8)*31 + ni], rB1 = Rs[(a0 +  8)*31 + ni + 16];
            float2 rA2 = Rs[(a0 + 16)*31 + ni], rB2 = Rs[(a0 + 16)*31 + ni + 16];
            float2 rA3 = Rs[(a0 + 24)*31 + ni], rB3 = Rs[(a0 + 24)*31 + ni + 16];
            float er, ei;
            er = rA0.x + sgn*rB0.x; ei = rA0.y + sgn*rB0.y; v0 += er*w.x - ei*w.y;
            er = rA1.x + sgn*rB1.x; ei = rA1.y + sgn*rB1.y; v1 += er*w.x - ei*w.y;
            er = rA2.x + sgn*rB2.x; ei = rA2.y + sgn*rB2.y; v2 += er*w.x - ei*w.y;
            er = rA3.x + sgn*rB3.x; ei = rA3.y + sgn*rB3.y; v3 += er*w.x - ei*w.y;
            float nr = w.x*step.x - w.y*step.y;
            w.y = w.x*step.y + w.y*step.x;
            w.x = nr;
        }
        v0 += Rs[(a0     )*31 + 15].x;
        v1 += Rs[(a0 +  8)*31 + 15].x;
        v2 += Rs[(a0 + 16)*31 + 15].x;
        v3 += Rs[(a0 + 24)*31 + 15].x;
        ys[(a0     )*32 + c] = fmaxf(v0, 0.f);
        ys[(a0 +  8)*32 + c] = fmaxf(v1, 0.f);
        ys[(a0 + 16)*32 + c] = fmaxf(v2, 0.f);
        ys[(a0 + 24)*32 + c] = fmaxf(v3, 0.f);
    }
    __syncthreads();

    // U[m,c] = sum_a y[a,c] e^{-i m a 2pi/32}, m=0..7
    {
        int m = tid >> 5, c = tid & 31;
        float2 st = tws[m]; st.y = -st.y;               // e^{-i m}
        float2 w = make_float2(1.f, 0.f);
        float sgn = (m & 1) ? -1.f : 1.f;
        float ur = 0.f, ui = 0.f;
        for (int a = 0; a < 16; a++) {
            float ye = ys[a*32 + c] + sgn*ys[(a+16)*32 + c];
            ur += ye*w.x; ui += ye*w.y;
            float nr = w.x*st.x - w.y*st.y;
            w.y = w.x*st.y + w.y*st.x;
            w.x = nr;
        }
        Us[tid] = make_float2(ur, ui);
    }
    __syncthreads();

    // V[m,n] = (1/1024) sum_c U[m,c] e^{-i n c 2pi/32}; mirror via conj sym
    const float s1 = 1.0f/1024.0f;
    size_t base = ((size_t)k*1024u + (size_t)(b*64+f))*225u;
    for (int idx = tid; idx < 120; idx += 256) {
        int m = idx/15, ni = idx%15, n = ni-7;
        float vr = 0.f, vi = 0.f;
        for (int c = 0; c < 32; c++) {
            int j = ((n+32)*c) & 31;
            float2 u = Us[m*32 + c];
            float2 t = tws[j];
            vr +=  u.x*t.x + u.y*t.y;
            vi += -u.x*t.y + u.y*t.x;
        }
        vr *= s1; vi *= s1;
        g_xf2[base + (m+7)*15 + ni] = make_float2(vr, vi);
        if (m > 0)
            g_xf2[base + (7-m)*15 + (14-ni)] = make_float2(vr, -vi);
    }
}

// ------------------------- Fx2 contraction over k --------------------------
__global__ void __launch_bounds__(256) k_fx2() {
    int bf0 = blockIdx.x * 4;                           // 256 blocks
    __shared__ float2 accs[NP2*4];
    __shared__ float2 tile[4*225];
    __shared__ float  coefs[NP2];
    __shared__ int    mns[NP2];
    int tid = threadIdx.x;
    for (int i = tid; i < NP2*4; i += 256) accs[i] = make_float2(0.f, 0.f);
    for (int i = tid; i < NP2;   i += 256) mns[i]  = g_mnidx[i];
    __syncthreads();
    for (int kk = 0; kk < 32; kk++) {
        for (int i = tid; i < 900; i += 256) {
            int j = i/225, mn = i%225;
            tile[j*225 + mn] = g_xf2[((size_t)kk*1024u + bf0 + j)*225u + mn];
        }
        for (int i = tid; i < NP2; i += 256) coefs[i] = g_cf1[kk*NP2 + i];
        __syncthreads();
        for (int i = tid; i < NP2*4; i += 256) {
            int p2 = i >> 2, j = i & 3;
            float  w = coefs[p2];
            float2 v = tile[j*225 + mns[p2]];
            accs[i].x += w*v.x;
            accs[i].y += w*v.y;
        }
        __syncthreads();
    }
    for (int i = tid; i < NP2*4; i += 256) {
        int p2 = i >> 2, j = i & 3;
        g_Fx2[(size_t)p2*1024u + bf0 + j] = accs[i];
    }
}

// ------------------------- Fy2 (conj) build --------------------------------
__global__ void __launch_bounds__(256) k_fy2(const float* __restrict__ w2) {
    __shared__ float  w2s[1024*9];
    __shared__ float2 psis[64];
    int p20 = blockIdx.x * 8;                           // 85 tiles
    int io0 = blockIdx.y * 1024;                        // 8 tiles
    int tid = threadIdx.x;
    float aR[8][4], aI[8][4];
    #pragma unroll
    for (int p = 0; p < 8; p++)
        #pragma unroll
        for (int q = 0; q < 4; q++) { aR[p][q] = 0.f; aI[p][q] = 0.f; }
    for (int gc = 0; gc < 192; gc += 8) {
        for (int i = tid; i < 8192; i += 256) {
            int iol = i >> 3, g = i & 7;
            w2s[iol*9 + g] = w2[(size_t)(io0+iol)*192 + gc + g];
        }
        if (tid < 64) {
            int pj = tid >> 3, g = tid & 7;
            psis[tid] = g_psi3[(p20+pj)*192 + gc + g];
        }
        __syncthreads();
        #pragma unroll
        for (int g = 0; g < 8; g++) {
            float pr[8], pim[8];
            #pragma unroll
            for (int pj = 0; pj < 8; pj++) {
                float2 v = psis[pj*8 + g];
                pr[pj] = v.x; pim[pj] = v.y;
            }
            #pragma unroll
            for (int ioj = 0; ioj < 4; ioj++) {
                float w = w2s[(ioj*256 + tid)*9 + g];
                #pragma unroll
                for (int pj = 0; pj < 8; pj++) {
                    aR[pj][ioj] += w*pr[pj];
                    aI[pj][ioj] += w*pim[pj];
                }
            }
        }
        __syncthreads();
    }
    #pragma unroll
    for (int pj = 0; pj < 8; pj++)
        #pragma unroll
        for (int ioj = 0; ioj < 4; ioj++)
            g_Fy2[(size_t)(p20+pj)*8192u + io0 + ioj*256 + tid] =
                make_float2(aR[pj][ioj], aI[pj][ioj]);
}

// ---------------- Fz2 batched complex GEMM (m>=0 half, split-k) ------------
__global__ void __launch_bounds__(256) k_fz2() {
    int bid2 = blockIdx.x;                              // 744 = 2 x 372
    int half = bid2 >= NH2;
    int jh = bid2 - half*NH2;
    int l = 0; while (c_choff[l+1] <= jh) l++;
    int r = jh - c_choff[l], D = 2*l+1;
    int mi = r / D, nio = r % D;                        // m = mi >= 0
    int kmid = (D+1) >> 1;
    int kw0 = half ? kmid : 0;
    int kw1 = half ? D : kmid;
    __shared__ float2 As[256];                          // [b16][ii16]
    __shared__ float2 Bs[2048];                         // [ii16][o128]
    int tid = threadIdx.x;
    int o = tid & 127, bh = tid >> 7;
    float aR[8], aI[8];
    #pragma unroll
    for (int j = 0; j < 8; j++) { aR[j] = 0.f; aI[j] = 0.f; }
    for (int kw = kw0; kw < kw1; kw++) {
        size_t p2A = (size_t)(c_off2[l] + (mi+l)*D + kw);
        size_t p2B = (size_t)(c_off2[l] + nio*D + kw);
        for (int ic = 0; ic < 4; ic++) {
            { int bb = tid >> 4, ii = tid & 15;
              As[tid] = g_Fx2[p2A*1024u + bb*64 + ic*16 + ii]; }
            for (int rr = tid; rr < 2048; rr += 256) {
                int ii = rr >> 7, oo = rr & 127;
                Bs[rr] = g_Fy2[p2B*8192u + (ic*16+ii)*128 + oo];
            }
            __syncthreads();
            #pragma unroll 4
            for (int ii = 0; ii < 16; ii++) {
                float2 bv = Bs[ii*128 + o];
                #pragma unroll
                for (int bj = 0; bj < 8; bj++) {
                    float2 av = As[(bh*8+bj)*16 + ii];
                    aR[bj] += av.x*bv.x - av.y*bv.y;
                    aI[bj] += av.x*bv.y + av.y*bv.x;
                }
            }
            __syncthreads();
        }
    }
    float2* dst = half ? g_Fz2hb : g_Fz2h;
    #pragma unroll
    for (int bj = 0; bj < 8; bj++) {
        int bb = bh*8 + bj;
        dst[(size_t)(bb*128 + o)*NH2 + jh] = make_float2(aR[bj], aI[bj]);
    }
}

// ------------------------- final fused iSO3 + relu + mean ------------------
__global__ void __launch_bounds__(256) k_final() {
    int bo = blockIdx.x;                                // 2048
    __shared__ float2 Fzs[NH2];
    __shared__ float  d2s[NH2];
    __shared__ float2 Ss[8*15];
    __shared__ float2 Rs[16*15];
    __shared__ float2 tws[16];
    __shared__ float  red[256];
    int tid = threadIdx.x;
    for (int i = tid; i < NH2; i += 256) {
        float2 a = g_Fz2h[(size_t)bo*NH2 + i];
        float2 b = g_Fz2hb[(size_t)bo*NH2 + i];
        Fzs[i] = make_float2(a.x + b.x, a.y + b.y);
    }
    if (tid < 16) {
        float s, c; sincosf((float)tid*(float)(2.0*PI_D/16.0), &s, &c);
        tws[tid] = make_float2(c, s);                   // e^{+2pi i j/16}
    }
    float accum = 0.f;
    for (int k2 = 0; k2 < 16; k2++) {
        for (int i = tid; i < NH2; i += 256) d2s[i] = g_dL2h[k2*NH2 + i];
        __syncthreads();
        if (tid < 120) {
            int mi = tid/15, ni = tid%15, n = ni-7;
            int an = n < 0 ? -n : n;
            int lmin = mi > an ? mi : an;
            int ch = (lmin*(lmin+1)*(4*lmin-1))/6;
            float sr = 0.f, si = 0.f;
            for (int l = lmin; l < 8; l++) {
                int D = 2*l+1;
                int p = ch + mi*D + n + l;
                float w = d2s[p];
                float2 fz = Fzs[p];
                sr += w*fz.x; si += w*fz.y;
                ch += (l+1)*D;
            }
            Ss[mi*15 + ni] = make_float2(sr, si);
        }
        __syncthreads();
        if (tid < 240) {
            int a = tid & 15, ni = tid >> 4;
            float2 step = tws[a];
            float2 w = make_float2(1.f, 0.f);
            float2 acc = {0,0};
            for (int m = 0; m < 8; m++) {
                float2 s = Ss[m*15 + ni];
                acc.x += s.x*w.x - s.y*w.y;
                acc.y += s.x*w.y + s.y*w.x;
                float nr = w.x*step.x - w.y*step.y;
                w.y = w.x*step.y + w.y*step.x;
                w.x = nr;
            }
            Rs[a*15 + ni] = acc;
        }
        __syncthreads();
        {
            int a = tid >> 4, c = tid & 15;
            float2 step = tws[c];
            float2 w = tws[(9*c) & 15];                 // e^{-i 7 c}
            float v = 0.f;
            for (int ni = 0; ni < 15; ni++) {
                float2 r = Rs[a*15 + ni];
                v += r.x*w.x - r.y*w.y;
                float nr = w.x*step.x - w.y*step.y;
                w.y = w.x*step.y + w.y*step.x;
                w.x = nr;
            }
            accum += fmaxf(v, 0.f) * g_Wl2[k2];
        }
        __syncthreads();
    }
    red[tid] = accum * (1.0f/256.0f);
    __syncthreads();
    for (int s = 128; s > 0; s >>= 1) {
        if (tid < s) red[tid] += red[tid + s];
        __syncthreads();
    }
    if (tid == 0) g_feat[bo] = red[0];
}

// ------------------------- linear head -------------------------------------
__global__ void k_head(const float* __restrict__ lw,
                       const float* __restrict__ lb,
                       float* __restrict__ out) {
    int t = threadIdx.x;
    if (t < 160) {
        int b = t / 10, j = t % 10;
        float s = lb[j];
        for (int o = 0; o < 128; o++)
            s += g_feat[b*128 + o] * lw[j*128 + o];
        out[t] = s;
    }
}

// ------------------------- launcher ----------------------------------------
extern "C" void kernel_launch(void* const* d_in, const int* in_sizes, int n_in,
                              void* d_out, int out_size) {
    const float* x  = (const float*)d_in[0];
    const float* w1 = (const float*)d_in[1];
    const float* w2 = (const float*)d_in[2];
    const float* lw = (const float*)d_in[3];
    const float* lb = (const float*)d_in[4];
    float* out = (float*)d_out;

    // ncu capture lands on my 4th launch -> k_mid is #4
    k_tables<<<918, 256>>>();                           // 1 (incl. weights)
    k_dft1<<<2048, 64>>>(x);                            // 2
    k_fxfyc<<<80, 256>>>(w1);                           // 3
    k_mid<<<32768, 256>>>();                            // 4  <- profiled
    k_prep<<<85, 256>>>();
    k_psi3gen<<<510, 256>>>();
    k_fx2<<<256, 256>>>();
    k_fy2<<<dim3(85, 8), 256>>>(w2);
    k_fz2<<<744, 256>>>();
    k_final<<<2048, 256>>>();
    k_head<<<1, 192>>>(lw, lb, out);
}